// round 13
// baseline (speedup 1.0000x reference)
#include <cuda_runtime.h>
#include <cuda_bf16.h>
#include <math_constants.h>
#include <cstdint>

// Problem shape (fixed): B=16, T=2048, C=512, H=64
#define BATCH 16
#define SEQ   2048
#define CDIM  512
#define HDIM  64
#define END_TOKEN 32000

#define ROWS_TOTAL (BATCH * SEQ)          // 32768
#define SCALE 0.04419417382415922f        // 512^-0.5
#define SCL2  0.06377946286456401f        // SCALE * log2(e)

__device__ __forceinline__ float tf32r(float x) {
    float y; asm("cvt.rna.tf32.f32 %0,%1;" : "=f"(y) : "f"(x)); return y;
}
__device__ __forceinline__ float ex2(float x) {
    float y; asm("ex2.approx.f32 %0,%1;" : "=f"(y) : "f"(x)); return y;
}
__device__ __forceinline__ uint32_t smem_u32(const void* p) {
    uint32_t a;
    asm("{ .reg .u64 t; cvta.to.shared.u64 t, %1; cvt.u32.u64 %0, t; }"
        : "=r"(a) : "l"(p));
    return a;
}
__device__ __forceinline__ void cp16(uint32_t dst, const void* src) {
    asm volatile("cp.async.cg.shared.global [%0], [%1], 16;"
                 :: "r"(dst), "l"(src) : "memory");
}
#define CP_COMMIT() asm volatile("cp.async.commit_group;" ::: "memory")
#define CP_WAIT0()  asm volatile("cp.async.wait_group 0;" ::: "memory")

// pair-permutation within 8: logical i -> physical (puts (i, i+4) adjacent)
__device__ __forceinline__ int perm8(int i) {
    return (i & ~7) | ((i & 3) << 1) | ((i >> 2) & 1);
}

// m16n8k8 tf32 mma (sm_80 portable feature -> fallback HMMA on sm_103)
__device__ __forceinline__ void mma_tf32(float* d, const uint32_t* a, const uint32_t* b) {
    asm volatile(
        "mma.sync.aligned.m16n8k8.row.col.f32.tf32.tf32.f32 "
        "{%0,%1,%2,%3}, {%4,%5,%6,%7}, {%8,%9}, {%0,%1,%2,%3};"
        : "+f"(d[0]), "+f"(d[1]), "+f"(d[2]), "+f"(d[3])
        : "r"(a[0]), "r"(a[1]), "r"(a[2]), "r"(a[3]), "r"(b[0]), "r"(b[1]));
}

// Scratch (allocation-free rule: __device__ globals)
// g_q: [row][perm8(h)] tf32(q*SCL2).  g_k: [row][perm8(h)] tf32.
// g_vt: [b][h][phi16(t)] tf32 (t interleaved within 16-blocks for LDS.128).
__device__ float g_q[ROWS_TOTAL * HDIM];
__device__ float g_k[ROWS_TOTAL * HDIM];
__device__ float g_vt[BATCH * HDIM * SEQ];
__device__ float g_wt[3 * HDIM * CDIM];   // W^T tf32: [mat][n][perm8(k)]
__device__ int   g_nlim[BATCH];           // SEQ - first_end (atomicMax; 0 = none)
// split-K partial results: 16 b x 8 heavy qt x 2 pieces
__device__ float g_po[BATCH * 8 * 2 * 128 * 64];   // unnormalized O
__device__ float g_pml[BATCH * 8 * 2 * 256];       // m[128] | l[128]
__device__ int   g_flag[BATCH * 8];                // merge tickets (reset by merger)

// Piece table (heavy-first). qt<8: single direct piece. qt>=8: two pieces.
__device__ const int PQT[24] = {7,8,9,10,11,12,13,14,15,15, 6,14, 5,13,
                                4,12, 3,11, 2,10, 1,9, 0,8};
__device__ const int PP1[24] = {0,0,0,0,0,0,0,0,0,1, 0,1, 0,1,
                                0,1, 0,1, 0,1, 0,1, 0,1};   // is piece1

// ---------------------------------------------------------------------------
// Kernel 0 (merged): blocks 0..47 transpose W (perm8 on k, tf32-rounded);
// blocks 48..175 scan idx for end tokens (8 blocks per batch, atomicMax —
// idempotent across graph replays; faithful to reference, never fires here).
// ---------------------------------------------------------------------------
__global__ void prep_kernel(const float* __restrict__ Wk,
                            const float* __restrict__ Wq,
                            const float* __restrict__ Wv,
                            const int* __restrict__ idx)
{
    if (blockIdx.x < 48) {
        const int m  = blockIdx.x / 16;
        const int ks = blockIdx.x % 16;           // k-slice of 32
        const float* src = (m == 0) ? Wq : (m == 1) ? Wk : Wv;
        float* dst = g_wt + (size_t)m * HDIM * CDIM;
        for (int i = threadIdx.x; i < 32 * 64; i += 256) {
            int k = ks * 32 + (i >> 6);
            int n = i & 63;
            dst[(size_t)n * CDIM + perm8(k)] = tf32r(src[(size_t)k * HDIM + n]);
        }
    } else {
        const int blk = blockIdx.x - 48;          // 0..127
        const int b   = blk >> 3;
        const int seg = blk & 7;
        const int t0  = seg * 256 + threadIdx.x;  // 1 element per thread
        if (idx[(size_t)b * SEQ + t0] == END_TOKEN)
            atomicMax(&g_nlim[b], SEQ - t0);
    }
}

// ---------------------------------------------------------------------------
// Kernel 1: QKV projection via tf32 mma.sync (64 rows x 192 cols per CTA).
// (unchanged from R12 — validated)
// ---------------------------------------------------------------------------
#define PJP 40

__global__ __launch_bounds__(256) void proj_kernel(const float* __restrict__ x)
{
    __shared__ float sbuf[64 * PJP + 192 * PJP];
    float* As = sbuf;
    float* Bs = sbuf + 64 * PJP;

    const int t    = threadIdx.x;
    const int wid  = t >> 5;
    const int lane = t & 31;
    const int g    = lane >> 2;
    const int ctg  = lane & 3;
    const int wm   = wid >> 2;
    const int wn   = wid & 3;
    const int row0 = blockIdx.x * 64;

    const int ar = t >> 2, af = (t & 3) * 8;
    const int br0 = t >> 2,           bf0 = (t & 3) * 8;
    const int br1 = (t + 256) >> 2,   bf1 = ((t + 256) & 3) * 8;
    const int br2 = (t + 512) >> 2,   bf2 = ((t + 512) & 3) * 8;

    float acc[2][6][4];
#pragma unroll
    for (int mt = 0; mt < 2; mt++)
#pragma unroll
        for (int nt = 0; nt < 6; nt++)
#pragma unroll
            for (int i = 0; i < 4; i++) acc[mt][nt][i] = 0.f;

    float4 pa0, pa1, pb[6];
    {
        const float* xp = x + (size_t)(row0 + ar) * CDIM + af;
        pa0 = *reinterpret_cast<const float4*>(xp);
        pa1 = *reinterpret_cast<const float4*>(xp + 4);
        pb[0] = *reinterpret_cast<const float4*>(g_wt + (size_t)br0 * CDIM + bf0);
        pb[1] = *reinterpret_cast<const float4*>(g_wt + (size_t)br0 * CDIM + bf0 + 4);
        pb[2] = *reinterpret_cast<const float4*>(g_wt + (size_t)br1 * CDIM + bf1);
        pb[3] = *reinterpret_cast<const float4*>(g_wt + (size_t)br1 * CDIM + bf1 + 4);
        pb[4] = *reinterpret_cast<const float4*>(g_wt + (size_t)br2 * CDIM + bf2);
        pb[5] = *reinterpret_cast<const float4*>(g_wt + (size_t)br2 * CDIM + bf2 + 4);
    }

    for (int kc = 0; kc < 16; kc++) {
        {
            float* a = &As[ar * PJP + af];
            *reinterpret_cast<float2*>(&a[0]) = make_float2(tf32r(pa0.x), tf32r(pa1.x));
            *reinterpret_cast<float2*>(&a[2]) = make_float2(tf32r(pa0.y), tf32r(pa1.y));
            *reinterpret_cast<float2*>(&a[4]) = make_float2(tf32r(pa0.z), tf32r(pa1.z));
            *reinterpret_cast<float2*>(&a[6]) = make_float2(tf32r(pa0.w), tf32r(pa1.w));
            *reinterpret_cast<float4*>(&Bs[br0 * PJP + bf0])     = pb[0];
            *reinterpret_cast<float4*>(&Bs[br0 * PJP + bf0 + 4]) = pb[1];
            *reinterpret_cast<float4*>(&Bs[br1 * PJP + bf1])     = pb[2];
            *reinterpret_cast<float4*>(&Bs[br1 * PJP + bf1 + 4]) = pb[3];
            *reinterpret_cast<float4*>(&Bs[br2 * PJP + bf2])     = pb[4];
            *reinterpret_cast<float4*>(&Bs[br2 * PJP + bf2 + 4]) = pb[5];
        }
        __syncthreads();

        if (kc < 15) {
            const int ko = (kc + 1) * 32;
            const float* xp = x + (size_t)(row0 + ar) * CDIM + ko + af;
            pa0 = *reinterpret_cast<const float4*>(xp);
            pa1 = *reinterpret_cast<const float4*>(xp + 4);
            pb[0] = *reinterpret_cast<const float4*>(g_wt + (size_t)br0 * CDIM + ko + bf0);
            pb[1] = *reinterpret_cast<const float4*>(g_wt + (size_t)br0 * CDIM + ko + bf0 + 4);
            pb[2] = *reinterpret_cast<const float4*>(g_wt + (size_t)br1 * CDIM + ko + bf1);
            pb[3] = *reinterpret_cast<const float4*>(g_wt + (size_t)br1 * CDIM + ko + bf1 + 4);
            pb[4] = *reinterpret_cast<const float4*>(g_wt + (size_t)br2 * CDIM + ko + bf2);
            pb[5] = *reinterpret_cast<const float4*>(g_wt + (size_t)br2 * CDIM + ko + bf2 + 4);
        }

#pragma unroll
        for (int ks = 0; ks < 4; ks++) {
            const int kb = ks * 8 + 2 * ctg;
            uint32_t a[2][4];
#pragma unroll
            for (int mt = 0; mt < 2; mt++) {
                int row = wm * 32 + mt * 16;
                float2 f0 = *reinterpret_cast<const float2*>(&As[(row + g) * PJP + kb]);
                float2 f1 = *reinterpret_cast<const float2*>(&As[(row + g + 8) * PJP + kb]);
                a[mt][0] = __float_as_uint(f0.x); a[mt][1] = __float_as_uint(f1.x);
                a[mt][2] = __float_as_uint(f0.y); a[mt][3] = __float_as_uint(f1.y);
            }
#pragma unroll
            for (int nt = 0; nt < 6; nt++) {
                int n = wn * 48 + nt * 8;
                float2 bf = *reinterpret_cast<const float2*>(&Bs[(n + g) * PJP + kb]);
                uint32_t b[2];
                b[0] = __float_as_uint(bf.x); b[1] = __float_as_uint(bf.y);
                mma_tf32(acc[0][nt], a[0], b);
                mma_tf32(acc[1][nt], a[1], b);
            }
        }
        __syncthreads();
    }

    float* Vtr = sbuf;
#pragma unroll
    for (int mt = 0; mt < 2; mt++) {
#pragma unroll
        for (int nt = 0; nt < 6; nt++) {
            int col = wn * 48 + nt * 8 + 2 * ctg;
            int mat = col >> 6, c0 = col & 63;
            int r0 = row0 + wm * 32 + mt * 16 + g;
            if (mat == 0) {   // Q: pre-scale by SCL2, perm8 on h
                g_q[(size_t)r0 * HDIM + perm8(c0)]           = tf32r(acc[mt][nt][0] * SCL2);
                g_q[(size_t)r0 * HDIM + perm8(c0 + 1)]       = tf32r(acc[mt][nt][1] * SCL2);
                g_q[(size_t)(r0 + 8) * HDIM + perm8(c0)]     = tf32r(acc[mt][nt][2] * SCL2);
                g_q[(size_t)(r0 + 8) * HDIM + perm8(c0 + 1)] = tf32r(acc[mt][nt][3] * SCL2);
            } else if (mat == 1) {   // K: perm8 on h
                g_k[(size_t)r0 * HDIM + perm8(c0)]           = tf32r(acc[mt][nt][0]);
                g_k[(size_t)r0 * HDIM + perm8(c0 + 1)]       = tf32r(acc[mt][nt][1]);
                g_k[(size_t)(r0 + 8) * HDIM + perm8(c0)]     = tf32r(acc[mt][nt][2]);
                g_k[(size_t)(r0 + 8) * HDIM + perm8(c0 + 1)] = tf32r(acc[mt][nt][3]);
            } else {   // V: phi16 interleave on t
                int tl  = wm * 32 + mt * 16 + g;
                int tlp = (tl & ~15) + 4 * (g >> 1) + (g & 1);   // phi16(tl)
                Vtr[c0 * 68 + tlp]             = tf32r(acc[mt][nt][0]);
                Vtr[(c0 + 1) * 68 + tlp]       = tf32r(acc[mt][nt][1]);
                Vtr[c0 * 68 + tlp + 2]         = tf32r(acc[mt][nt][2]);  // phi16(tl+8)
                Vtr[(c0 + 1) * 68 + tlp + 2]   = tf32r(acc[mt][nt][3]);
            }
        }
    }
    __syncthreads();

    {
        const int b  = row0 >> 11;
        const int t0 = row0 & 2047;
#pragma unroll
        for (int i = 0; i < 4; i++) {
            int idx = t + 256 * i;
            int h = idx >> 4, c = (idx & 15) * 4;
            float4 v = *reinterpret_cast<const float4*>(&Vtr[h * 68 + c]);
            *reinterpret_cast<float4*>(
                &g_vt[((size_t)b * HDIM + h) * SEQ + t0 + c]) = v;
        }
    }
}

// ---------------------------------------------------------------------------
// Kernel 2: causal flash attention, split-K pieces with fused ticketed merge.
// ---------------------------------------------------------------------------
#define QP 72
#define VP 80
#define OFF_KB(buf) (128 * QP + (buf) * 64 * QP)
#define OFF_VB(buf) (128 * QP + 2 * 64 * QP + (buf) * 64 * VP)
#define ATTN_SMEM_FLOATS (128 * QP + 2 * 64 * QP + 2 * 64 * VP)
#define ATTN_SMEM_BYTES (ATTN_SMEM_FLOATS * 4)

__global__ __launch_bounds__(256, 2) void attn_kernel(float* __restrict__ out)
{
    extern __shared__ float smf[];
    const uint32_t smb = smem_u32(smf);

    const int t    = threadIdx.x;
    const int wid  = t >> 5;
    const int lane = t & 31;
    const int g    = lane >> 2;
    const int ctg  = lane & 3;
    const int qw   = wid * 16;
    const int b    = blockIdx.x;
    const int pc   = blockIdx.y;
    const int qt   = PQT[pc];
    const int p1   = PP1[pc];
    const bool split = (qt >= 8);
    const int ks   = p1 ? 16 : 0;
    const int ke   = (split && !p1) ? 16 : (2 * qt + 2);
    const int q0   = qt * 128;

    const float* kg0 = g_k  + ((size_t)b * SEQ) * HDIM;
    const float* vg0 = g_vt + ((size_t)b * HDIM) * SEQ;

    // stage Q
    {
        const float* qg = g_q + ((size_t)b * SEQ + q0) * HDIM;
#pragma unroll
        for (int i = 0; i < 8; i++) {
            int idx = t + 256 * i;
            int r = idx >> 4, c = (idx & 15) * 4;
            cp16(smb + (uint32_t)(r * QP + c) * 4, qg + (size_t)r * HDIM + c);
        }
    }
    // stage K/V block ks into buf 0
    {
        const float* kg = kg0 + (size_t)ks * 64 * HDIM;
        const float* vg = vg0 + (size_t)ks * 64;
#pragma unroll
        for (int i = 0; i < 4; i++) {
            int idx = t + 256 * i;
            int r = idx >> 4, c = (idx & 15) * 4;
            cp16(smb + (uint32_t)(OFF_KB(0) + r * QP + c) * 4,
                 kg + (size_t)r * HDIM + c);
            cp16(smb + (uint32_t)(OFF_VB(0) + r * VP + c) * 4,
                 vg + (size_t)r * SEQ + c);
        }
    }
    CP_COMMIT(); CP_WAIT0(); __syncthreads();

    float mrow[2] = { -CUDART_INF_F, -CUDART_INF_F };   // log2 domain
    float lrow[2] = { 0.f, 0.f };
    float o[8][4];
#pragma unroll
    for (int nt = 0; nt < 8; nt++)
#pragma unroll
        for (int i = 0; i < 4; i++) o[nt][i] = 0.f;

    for (int kt = ks; kt < ke; kt++) {
        const int cur = (kt - ks) & 1;

        if (kt + 1 < ke) {
            const float* kg = kg0 + (size_t)(kt + 1) * 64 * HDIM;
            const float* vg = vg0 + (size_t)(kt + 1) * 64;
#pragma unroll
            for (int i = 0; i < 4; i++) {
                int idx = t + 256 * i;
                int r = idx >> 4, c = (idx & 15) * 4;
                cp16(smb + (uint32_t)(OFF_KB(cur ^ 1) + r * QP + c) * 4,
                     kg + (size_t)r * HDIM + c);
                cp16(smb + (uint32_t)(OFF_VB(cur ^ 1) + r * VP + c) * 4,
                     vg + (size_t)r * SEQ + c);
            }
        }
        CP_COMMIT();

        const float* Kb = smf + OFF_KB(cur);
        const float* Vb = smf + OFF_VB(cur);

        // ---- S = Q K^T (Q pre-scaled) ----
        float s[8][4];
#pragma unroll
        for (int nt = 0; nt < 8; nt++)
#pragma unroll
            for (int i = 0; i < 4; i++) s[nt][i] = 0.f;

#pragma unroll
        for (int kss = 0; kss < 8; kss++) {
            const int kb = kss * 8 + 2 * ctg;
            float2 qa0 = *reinterpret_cast<const float2*>(&smf[(qw + g) * QP + kb]);
            float2 qa1 = *reinterpret_cast<const float2*>(&smf[(qw + g + 8) * QP + kb]);
            uint32_t a[4];
            a[0] = __float_as_uint(qa0.x); a[1] = __float_as_uint(qa1.x);
            a[2] = __float_as_uint(qa0.y); a[3] = __float_as_uint(qa1.y);
#pragma unroll
            for (int nt = 0; nt < 8; nt++) {
                float2 kf = *reinterpret_cast<const float2*>(&Kb[(nt * 8 + g) * QP + kb]);
                uint32_t bb[2];
                bb[0] = __float_as_uint(kf.x); bb[1] = __float_as_uint(kf.y);
                mma_tf32(s[nt], a, bb);
            }
        }

        // ---- causal mask + online softmax (log2 domain; S pre-scaled) ----
        const bool tail = (kt >= 2 * qt);
        const int r0gl = q0 + qw + g, r1gl = r0gl + 8;
        const int kbase = kt * 64;
        float rm0 = -CUDART_INF_F, rm1 = -CUDART_INF_F;
#pragma unroll
        for (int nt = 0; nt < 8; nt++) {
            int cl = kbase + nt * 8 + 2 * ctg;
#pragma unroll
            for (int c = 0; c < 2; c++) {
                float v0 = s[nt][c];
                float v1 = s[nt][2 + c];
                if (tail) {
                    if (cl + c > r0gl) v0 = -1e30f;
                    if (cl + c > r1gl) v1 = -1e30f;
                }
                s[nt][c] = v0; s[nt][2 + c] = v1;
                rm0 = fmaxf(rm0, v0); rm1 = fmaxf(rm1, v1);
            }
        }
        rm0 = fmaxf(rm0, __shfl_xor_sync(0xffffffffu, rm0, 1));
        rm0 = fmaxf(rm0, __shfl_xor_sync(0xffffffffu, rm0, 2));
        rm1 = fmaxf(rm1, __shfl_xor_sync(0xffffffffu, rm1, 1));
        rm1 = fmaxf(rm1, __shfl_xor_sync(0xffffffffu, rm1, 2));

        float mn0 = fmaxf(mrow[0], rm0), mn1 = fmaxf(mrow[1], rm1);
        float fc0 = ex2(mrow[0] - mn0), fc1 = ex2(mrow[1] - mn1);
        float rs0 = 0.f, rs1 = 0.f;
#pragma unroll
        for (int nt = 0; nt < 8; nt++) {
#pragma unroll
            for (int c = 0; c < 2; c++) {
                float p0 = ex2(s[nt][c] - mn0);
                float p1 = ex2(s[nt][2 + c] - mn1);
                s[nt][c] = p0; s[nt][2 + c] = p1;
                rs0 += p0; rs1 += p1;
            }
        }
        rs0 += __shfl_xor_sync(0xffffffffu, rs0, 1);
        rs0 += __shfl_xor_sync(0xffffffffu, rs0, 2);
        rs1 += __shfl_xor_sync(0xffffffffu, rs1, 1);
        rs1 += __shfl_xor_sync(0xffffffffu, rs1, 2);

        lrow[0] = lrow[0] * fc0 + rs0;
        lrow[1] = lrow[1] * fc1 + rs1;
        mrow[0] = mn0; mrow[1] = mn1;
#pragma unroll
        for (int nt = 0; nt < 8; nt++) {
            o[nt][0] *= fc0; o[nt][1] *= fc0;
            o[nt][2] *= fc1; o[nt][3] *= fc1;
        }

        // ---- O += P V : LDS.128 V fragments serve ks-pairs (phi16 layout) ----
#pragma unroll
        for (int u = 0; u < 4; u++) {
            uint32_t a0[4], a1[4];
            a0[0] = __float_as_uint(s[2*u][0]);
            a0[1] = __float_as_uint(s[2*u][2]);
            a0[2] = __float_as_uint(s[2*u][1]);
            a0[3] = __float_as_uint(s[2*u][3]);
            a1[0] = __float_as_uint(s[2*u+1][0]);
            a1[1] = __float_as_uint(s[2*u+1][2]);
            a1[2] = __float_as_uint(s[2*u+1][1]);
            a1[3] = __float_as_uint(s[2*u+1][3]);
            const int kb = 16 * u + 4 * ctg;
#pragma unroll
            for (int nt = 0; nt < 8; nt++) {
                float4 vf = *reinterpret_cast<const float4*>(&Vb[(nt * 8 + g) * VP + kb]);
                uint32_t b0[2], b1[2];
                b0[0] = __float_as_uint(vf.x); b0[1] = __float_as_uint(vf.y);
                b1[0] = __float_as_uint(vf.z); b1[1] = __float_as_uint(vf.w);
                mma_tf32(o[nt], a0, b0);
                mma_tf32(o[nt], a1, b1);
            }
        }

        CP_WAIT0();
        __syncthreads();
    }

    // ---- epilogue ----
    const int limit = SEQ - g_nlim[b];
    const float qnan = __int_as_float(0x7FC00000);

    if (!split) {
        const int q0g = q0 + qw + g;
        const float inv0 = 1.f / lrow[0];
        const float inv1 = 1.f / lrow[1];
#pragma unroll
        for (int nt = 0; nt < 8; nt++) {
            int col = nt * 8 + 2 * ctg;
            float2 r0v, r1v;
            if (q0g >= limit) r0v = make_float2(qnan, qnan);
            else r0v = make_float2(o[nt][0] * inv0, o[nt][1] * inv0);
            if (q0g + 8 >= limit) r1v = make_float2(qnan, qnan);
            else r1v = make_float2(o[nt][2] * inv1, o[nt][3] * inv1);
            *reinterpret_cast<float2*>(&out[((size_t)b * SEQ + q0g) * HDIM + col]) = r0v;
            *reinterpret_cast<float2*>(&out[((size_t)b * SEQ + q0g + 8) * HDIM + col]) = r1v;
        }
        return;
    }

    // split piece: publish partial, take ticket; second finisher merges.
    const int slotb = b * 8 + (qt - 8);
    const int slot  = slotb * 2 + p1;
    {
        float* po  = g_po  + (size_t)slot * 8192;
        float* pml = g_pml + (size_t)slot * 256;
        const int r0l = qw + g, r1l = r0l + 8;
#pragma unroll
        for (int nt = 0; nt < 8; nt++) {
            int col = nt * 8 + 2 * ctg;
            *reinterpret_cast<float2*>(&po[r0l * 64 + col]) =
                make_float2(o[nt][0], o[nt][1]);
            *reinterpret_cast<float2*>(&po[r1l * 64 + col]) =
                make_float2(o[nt][2], o[nt][3]);
        }
        if (ctg == 0) {
            pml[r0l] = mrow[0]; pml[128 + r0l] = lrow[0];
            pml[r1l] = mrow[1]; pml[128 + r1l] = lrow[1];
        }
    }
    __threadfence();
    __syncthreads();
    __shared__ int s_old;
    if (t == 0) s_old = atomicAdd(&g_flag[slotb], 1);
    __syncthreads();
    if (s_old == 0) return;                 // first finisher: done
    if (t == 0) g_flag[slotb] = 0;          // reset for next graph replay
    __threadfence();

    // merge (deterministic: operands assigned by slot index, not arrival)
    {
        const int sib = slotb * 2 + (p1 ^ 1);
        const float* so  = g_po  + (size_t)sib * 8192;
        const float* sml = g_pml + (size_t)sib * 256;
        const int r0l = qw + g, r1l = r0l + 8;

        float inv[2], fown[2], fsib[2];
#pragma unroll
        for (int i = 0; i < 2; i++) {
            int r = (i == 0) ? r0l : r1l;
            float ms = sml[r], ls = sml[128 + r];
            float mo = mrow[i], lo = lrow[i];
            // slot-ordered: piece0 operand first
            float m_0 = p1 ? ms : mo, l_0 = p1 ? ls : lo;
            float m_1 = p1 ? mo : ms, l_1 = p1 ? lo : ls;
            float mm = fmaxf(m_0, m_1);
            float f0 = ex2(m_0 - mm), f1 = ex2(m_1 - mm);
            inv[i]  = 1.f / __fmaf_rn(l_1, f1, l_0 * f0);
            fown[i] = p1 ? f1 : f0;
            fsib[i] = p1 ? f0 : f1;
        }

        const int q0g = q0 + r0l;
#pragma unroll
        for (int nt = 0; nt < 8; nt++) {
            int col = nt * 8 + 2 * ctg;
            float2 s0 = *reinterpret_cast<const float2*>(&so[r0l * 64 + col]);
            float2 s1 = *reinterpret_cast<const float2*>(&so[r1l * 64 + col]);
            float2 r0v, r1v;
            if (q0g >= limit) r0v = make_float2(qnan, qnan);
            else {
                // slot-ordered sum: O0*f0 + O1*f1  (own/sib mapped via fown/fsib)
                r0v.x = __fmaf_rn(o[nt][0], fown[0], s0.x * fsib[0]) * inv[0];
                r0v.y = __fmaf_rn(o[nt][1], fown[0], s0.y * fsib[0]) * inv[0];
            }
            if (q0g + 8 >= limit) r1v = make_float2(qnan, qnan);
            else {
                r1v.x = __fmaf_rn(o[nt][2], fown[1], s1.x * fsib[1]) * inv[1];
                r1v.y = __fmaf_rn(o[nt][3], fown[1], s1.y * fsib[1]) * inv[1];
            }
            *reinterpret_cast<float2*>(&out[((size_t)b * SEQ + q0g) * HDIM + col]) = r0v;
            *reinterpret_cast<float2*>(&out[((size_t)b * SEQ + q0g + 8) * HDIM + col]) = r1v;
        }
    }
}

// ---------------------------------------------------------------------------
extern "C" void kernel_launch(void* const* d_in, const int* in_sizes, int n_in,
                              void* d_out, int out_size)
{
    const float* x  = (const float*)d_in[0];
    const float* Wk = (const float*)d_in[1];
    const float* Wq = (const float*)d_in[2];
    const float* Wv = (const float*)d_in[3];
    const int*  idx = (const int*)d_in[4];
    float* out = (float*)d_out;

    (void)in_sizes; (void)n_in; (void)out_size;

    cudaFuncSetAttribute(attn_kernel,
                         cudaFuncAttributeMaxDynamicSharedMemorySize,
                         ATTN_SMEM_BYTES);

    prep_kernel<<<176, 256>>>(Wk, Wq, Wv, idx);
    proj_kernel<<<ROWS_TOTAL / 64, 256>>>(x);
    attn_kernel<<<dim3(BATCH, 24), 256, ATTN_SMEM_BYTES>>>(out);
}

// round 14
// speedup vs baseline: 1.0661x; 1.0661x over previous
#include <cuda_runtime.h>
#include <cuda_bf16.h>
#include <math_constants.h>
#include <cstdint>

// Problem shape (fixed): B=16, T=2048, C=512, H=64
#define BATCH 16
#define SEQ   2048
#define CDIM  512
#define HDIM  64
#define END_TOKEN 32000

#define ROWS_TOTAL (BATCH * SEQ)          // 32768
#define SCALE 0.04419417382415922f        // 512^-0.5
#define SCL2  0.06377946286456401f        // SCALE * log2(e)

__device__ __forceinline__ float tf32r(float x) {
    float y; asm("cvt.rna.tf32.f32 %0,%1;" : "=f"(y) : "f"(x)); return y;
}
__device__ __forceinline__ float ex2(float x) {
    float y; asm("ex2.approx.f32 %0,%1;" : "=f"(y) : "f"(x)); return y;
}
__device__ __forceinline__ uint32_t smem_u32(const void* p) {
    uint32_t a;
    asm("{ .reg .u64 t; cvta.to.shared.u64 t, %1; cvt.u32.u64 %0, t; }"
        : "=r"(a) : "l"(p));
    return a;
}
__device__ __forceinline__ void cp16(uint32_t dst, const void* src) {
    asm volatile("cp.async.cg.shared.global [%0], [%1], 16;"
                 :: "r"(dst), "l"(src) : "memory");
}
#define CP_COMMIT() asm volatile("cp.async.commit_group;" ::: "memory")
#define CP_WAIT0()  asm volatile("cp.async.wait_group 0;" ::: "memory")

// pair-permutation within 8: logical i -> physical (puts (i, i+4) adjacent)
__device__ __forceinline__ int perm8(int i) {
    return (i & ~7) | ((i & 3) << 1) | ((i >> 2) & 1);
}

// m16n8k8 tf32 mma (sm_80 portable feature -> fallback HMMA on sm_103)
__device__ __forceinline__ void mma_tf32(float* d, const uint32_t* a, const uint32_t* b) {
    asm volatile(
        "mma.sync.aligned.m16n8k8.row.col.f32.tf32.tf32.f32 "
        "{%0,%1,%2,%3}, {%4,%5,%6,%7}, {%8,%9}, {%0,%1,%2,%3};"
        : "+f"(d[0]), "+f"(d[1]), "+f"(d[2]), "+f"(d[3])
        : "r"(a[0]), "r"(a[1]), "r"(a[2]), "r"(a[3]), "r"(b[0]), "r"(b[1]));
}

// Scratch (allocation-free rule: __device__ globals)
// g_q: [row][perm8(h)] tf32(q*SCL2).  g_k: [row][perm8(h)] tf32.
// g_vt: [b][h][phi16(t)] tf32 (t interleaved within 16-blocks for LDS.128).
__device__ float g_q[ROWS_TOTAL * HDIM];
__device__ float g_k[ROWS_TOTAL * HDIM];
__device__ float g_vt[BATCH * HDIM * SEQ];
__device__ float g_wt[3 * HDIM * CDIM];   // W^T tf32: [mat][n][perm8(k)]
__device__ int   g_limit[BATCH];
// split-K partial results: 16 b x 8 heavy qt x 2 pieces
__device__ float g_po[BATCH * 8 * 2 * 128 * 64];   // unnormalized O
__device__ float g_pml[BATCH * 8 * 2 * 256];       // m[128] | l[128]

// Piece table (heavy-first). qt<8: single direct piece. qt>=8: two pieces.
__device__ const int PQT[24] = {7,8,9,10,11,12,13,14,15,15, 6,14, 5,13,
                                4,12, 3,11, 2,10, 1,9, 0,8};
__device__ const int PP1[24] = {0,0,0,0,0,0,0,0,0,1, 0,1, 0,1,
                                0,1, 0,1, 0,1, 0,1, 0,1};   // is piece1

// ---------------------------------------------------------------------------
// Kernel 0 (merged): blocks 0..47 transpose W (perm8 on k, tf32-rounded);
// blocks 48..63 run the end-token scan (faithful; never fires here).
// ---------------------------------------------------------------------------
__global__ void prep_kernel(const float* __restrict__ Wk,
                            const float* __restrict__ Wq,
                            const float* __restrict__ Wv,
                            const int* __restrict__ idx)
{
    if (blockIdx.x < 48) {
        const int m  = blockIdx.x / 16;
        const int ks = blockIdx.x % 16;           // k-slice of 32
        const float* src = (m == 0) ? Wq : (m == 1) ? Wk : Wv;
        float* dst = g_wt + (size_t)m * HDIM * CDIM;
        for (int i = threadIdx.x; i < 32 * 64; i += 256) {
            int k = ks * 32 + (i >> 6);
            int n = i & 63;
            dst[(size_t)n * CDIM + perm8(k)] = tf32r(src[(size_t)k * HDIM + n]);
        }
    } else {
        __shared__ int best;
        if (threadIdx.x == 0) best = SEQ;
        __syncthreads();
        const int b = blockIdx.x - 48;
        for (int t = threadIdx.x; t < SEQ; t += blockDim.x)
            if (idx[(size_t)b * SEQ + t] == END_TOKEN) atomicMin(&best, t);
        __syncthreads();
        if (threadIdx.x == 0) g_limit[b] = best;
    }
}

// ---------------------------------------------------------------------------
// Kernel 1: QKV projection via tf32 mma.sync (64 rows x 192 cols per CTA).
// (unchanged — validated R12)
// ---------------------------------------------------------------------------
#define PJP 40

__global__ __launch_bounds__(256) void proj_kernel(const float* __restrict__ x)
{
    __shared__ float sbuf[64 * PJP + 192 * PJP];
    float* As = sbuf;
    float* Bs = sbuf + 64 * PJP;

    const int t    = threadIdx.x;
    const int wid  = t >> 5;
    const int lane = t & 31;
    const int g    = lane >> 2;
    const int ctg  = lane & 3;
    const int wm   = wid >> 2;
    const int wn   = wid & 3;
    const int row0 = blockIdx.x * 64;

    const int ar = t >> 2, af = (t & 3) * 8;
    const int br0 = t >> 2,           bf0 = (t & 3) * 8;
    const int br1 = (t + 256) >> 2,   bf1 = ((t + 256) & 3) * 8;
    const int br2 = (t + 512) >> 2,   bf2 = ((t + 512) & 3) * 8;

    float acc[2][6][4];
#pragma unroll
    for (int mt = 0; mt < 2; mt++)
#pragma unroll
        for (int nt = 0; nt < 6; nt++)
#pragma unroll
            for (int i = 0; i < 4; i++) acc[mt][nt][i] = 0.f;

    float4 pa0, pa1, pb[6];
    {
        const float* xp = x + (size_t)(row0 + ar) * CDIM + af;
        pa0 = *reinterpret_cast<const float4*>(xp);
        pa1 = *reinterpret_cast<const float4*>(xp + 4);
        pb[0] = *reinterpret_cast<const float4*>(g_wt + (size_t)br0 * CDIM + bf0);
        pb[1] = *reinterpret_cast<const float4*>(g_wt + (size_t)br0 * CDIM + bf0 + 4);
        pb[2] = *reinterpret_cast<const float4*>(g_wt + (size_t)br1 * CDIM + bf1);
        pb[3] = *reinterpret_cast<const float4*>(g_wt + (size_t)br1 * CDIM + bf1 + 4);
        pb[4] = *reinterpret_cast<const float4*>(g_wt + (size_t)br2 * CDIM + bf2);
        pb[5] = *reinterpret_cast<const float4*>(g_wt + (size_t)br2 * CDIM + bf2 + 4);
    }

    for (int kc = 0; kc < 16; kc++) {
        {
            float* a = &As[ar * PJP + af];
            *reinterpret_cast<float2*>(&a[0]) = make_float2(tf32r(pa0.x), tf32r(pa1.x));
            *reinterpret_cast<float2*>(&a[2]) = make_float2(tf32r(pa0.y), tf32r(pa1.y));
            *reinterpret_cast<float2*>(&a[4]) = make_float2(tf32r(pa0.z), tf32r(pa1.z));
            *reinterpret_cast<float2*>(&a[6]) = make_float2(tf32r(pa0.w), tf32r(pa1.w));
            *reinterpret_cast<float4*>(&Bs[br0 * PJP + bf0])     = pb[0];
            *reinterpret_cast<float4*>(&Bs[br0 * PJP + bf0 + 4]) = pb[1];
            *reinterpret_cast<float4*>(&Bs[br1 * PJP + bf1])     = pb[2];
            *reinterpret_cast<float4*>(&Bs[br1 * PJP + bf1 + 4]) = pb[3];
            *reinterpret_cast<float4*>(&Bs[br2 * PJP + bf2])     = pb[4];
            *reinterpret_cast<float4*>(&Bs[br2 * PJP + bf2 + 4]) = pb[5];
        }
        __syncthreads();

        if (kc < 15) {
            const int ko = (kc + 1) * 32;
            const float* xp = x + (size_t)(row0 + ar) * CDIM + ko + af;
            pa0 = *reinterpret_cast<const float4*>(xp);
            pa1 = *reinterpret_cast<const float4*>(xp + 4);
            pb[0] = *reinterpret_cast<const float4*>(g_wt + (size_t)br0 * CDIM + ko + bf0);
            pb[1] = *reinterpret_cast<const float4*>(g_wt + (size_t)br0 * CDIM + ko + bf0 + 4);
            pb[2] = *reinterpret_cast<const float4*>(g_wt + (size_t)br1 * CDIM + ko + bf1);
            pb[3] = *reinterpret_cast<const float4*>(g_wt + (size_t)br1 * CDIM + ko + bf1 + 4);
            pb[4] = *reinterpret_cast<const float4*>(g_wt + (size_t)br2 * CDIM + ko + bf2);
            pb[5] = *reinterpret_cast<const float4*>(g_wt + (size_t)br2 * CDIM + ko + bf2 + 4);
        }

#pragma unroll
        for (int ks = 0; ks < 4; ks++) {
            const int kb = ks * 8 + 2 * ctg;
            uint32_t a[2][4];
#pragma unroll
            for (int mt = 0; mt < 2; mt++) {
                int row = wm * 32 + mt * 16;
                float2 f0 = *reinterpret_cast<const float2*>(&As[(row + g) * PJP + kb]);
                float2 f1 = *reinterpret_cast<const float2*>(&As[(row + g + 8) * PJP + kb]);
                a[mt][0] = __float_as_uint(f0.x); a[mt][1] = __float_as_uint(f1.x);
                a[mt][2] = __float_as_uint(f0.y); a[mt][3] = __float_as_uint(f1.y);
            }
#pragma unroll
            for (int nt = 0; nt < 6; nt++) {
                int n = wn * 48 + nt * 8;
                float2 bf = *reinterpret_cast<const float2*>(&Bs[(n + g) * PJP + kb]);
                uint32_t b[2];
                b[0] = __float_as_uint(bf.x); b[1] = __float_as_uint(bf.y);
                mma_tf32(acc[0][nt], a[0], b);
                mma_tf32(acc[1][nt], a[1], b);
            }
        }
        __syncthreads();
    }

    float* Vtr = sbuf;
#pragma unroll
    for (int mt = 0; mt < 2; mt++) {
#pragma unroll
        for (int nt = 0; nt < 6; nt++) {
            int col = wn * 48 + nt * 8 + 2 * ctg;
            int mat = col >> 6, c0 = col & 63;
            int r0 = row0 + wm * 32 + mt * 16 + g;
            if (mat == 0) {   // Q: pre-scale by SCL2, perm8 on h
                g_q[(size_t)r0 * HDIM + perm8(c0)]           = tf32r(acc[mt][nt][0] * SCL2);
                g_q[(size_t)r0 * HDIM + perm8(c0 + 1)]       = tf32r(acc[mt][nt][1] * SCL2);
                g_q[(size_t)(r0 + 8) * HDIM + perm8(c0)]     = tf32r(acc[mt][nt][2] * SCL2);
                g_q[(size_t)(r0 + 8) * HDIM + perm8(c0 + 1)] = tf32r(acc[mt][nt][3] * SCL2);
            } else if (mat == 1) {   // K: perm8 on h
                g_k[(size_t)r0 * HDIM + perm8(c0)]           = tf32r(acc[mt][nt][0]);
                g_k[(size_t)r0 * HDIM + perm8(c0 + 1)]       = tf32r(acc[mt][nt][1]);
                g_k[(size_t)(r0 + 8) * HDIM + perm8(c0)]     = tf32r(acc[mt][nt][2]);
                g_k[(size_t)(r0 + 8) * HDIM + perm8(c0 + 1)] = tf32r(acc[mt][nt][3]);
            } else {   // V: phi16 interleave on t
                int tl  = wm * 32 + mt * 16 + g;
                int tlp = (tl & ~15) + 4 * (g >> 1) + (g & 1);   // phi16(tl)
                Vtr[c0 * 68 + tlp]             = tf32r(acc[mt][nt][0]);
                Vtr[(c0 + 1) * 68 + tlp]       = tf32r(acc[mt][nt][1]);
                Vtr[c0 * 68 + tlp + 2]         = tf32r(acc[mt][nt][2]);  // phi16(tl+8)
                Vtr[(c0 + 1) * 68 + tlp + 2]   = tf32r(acc[mt][nt][3]);
            }
        }
    }
    __syncthreads();

    {
        const int b  = row0 >> 11;
        const int t0 = row0 & 2047;
#pragma unroll
        for (int i = 0; i < 4; i++) {
            int idx = t + 256 * i;
            int h = idx >> 4, c = (idx & 15) * 4;
            float4 v = *reinterpret_cast<const float4*>(&Vtr[h * 68 + c]);
            *reinterpret_cast<float4*>(
                &g_vt[((size_t)b * HDIM + h) * SEQ + t0 + c]) = v;
        }
    }
}

// ---------------------------------------------------------------------------
// Kernel 2: causal flash attention, split-K pieces (unchanged — validated R12).
// ---------------------------------------------------------------------------
#define QP 72
#define VP 80
#define OFF_KB(buf) (128 * QP + (buf) * 64 * QP)
#define OFF_VB(buf) (128 * QP + 2 * 64 * QP + (buf) * 64 * VP)
#define ATTN_SMEM_FLOATS (128 * QP + 2 * 64 * QP + 2 * 64 * VP)
#define ATTN_SMEM_BYTES (ATTN_SMEM_FLOATS * 4)

__global__ __launch_bounds__(256, 2) void attn_kernel(float* __restrict__ out)
{
    extern __shared__ float smf[];
    const uint32_t smb = smem_u32(smf);

    const int t    = threadIdx.x;
    const int wid  = t >> 5;
    const int lane = t & 31;
    const int g    = lane >> 2;
    const int ctg  = lane & 3;
    const int qw   = wid * 16;
    const int b    = blockIdx.x;
    const int pc   = blockIdx.y;
    const int qt   = PQT[pc];
    const int p1   = PP1[pc];
    const bool split = (qt >= 8);
    const int ks   = p1 ? 16 : 0;
    const int ke   = (split && !p1) ? 16 : (2 * qt + 2);
    const int q0   = qt * 128;

    const float* kg0 = g_k  + ((size_t)b * SEQ) * HDIM;
    const float* vg0 = g_vt + ((size_t)b * HDIM) * SEQ;

    // stage Q
    {
        const float* qg = g_q + ((size_t)b * SEQ + q0) * HDIM;
#pragma unroll
        for (int i = 0; i < 8; i++) {
            int idx = t + 256 * i;
            int r = idx >> 4, c = (idx & 15) * 4;
            cp16(smb + (uint32_t)(r * QP + c) * 4, qg + (size_t)r * HDIM + c);
        }
    }
    // stage K/V block ks into buf 0
    {
        const float* kg = kg0 + (size_t)ks * 64 * HDIM;
        const float* vg = vg0 + (size_t)ks * 64;
#pragma unroll
        for (int i = 0; i < 4; i++) {
            int idx = t + 256 * i;
            int r = idx >> 4, c = (idx & 15) * 4;
            cp16(smb + (uint32_t)(OFF_KB(0) + r * QP + c) * 4,
                 kg + (size_t)r * HDIM + c);
            cp16(smb + (uint32_t)(OFF_VB(0) + r * VP + c) * 4,
                 vg + (size_t)r * SEQ + c);
        }
    }
    CP_COMMIT(); CP_WAIT0(); __syncthreads();

    float mrow[2] = { -CUDART_INF_F, -CUDART_INF_F };   // log2 domain
    float lrow[2] = { 0.f, 0.f };
    float o[8][4];
#pragma unroll
    for (int nt = 0; nt < 8; nt++)
#pragma unroll
        for (int i = 0; i < 4; i++) o[nt][i] = 0.f;

    for (int kt = ks; kt < ke; kt++) {
        const int cur = (kt - ks) & 1;

        if (kt + 1 < ke) {
            const float* kg = kg0 + (size_t)(kt + 1) * 64 * HDIM;
            const float* vg = vg0 + (size_t)(kt + 1) * 64;
#pragma unroll
            for (int i = 0; i < 4; i++) {
                int idx = t + 256 * i;
                int r = idx >> 4, c = (idx & 15) * 4;
                cp16(smb + (uint32_t)(OFF_KB(cur ^ 1) + r * QP + c) * 4,
                     kg + (size_t)r * HDIM + c);
                cp16(smb + (uint32_t)(OFF_VB(cur ^ 1) + r * VP + c) * 4,
                     vg + (size_t)r * SEQ + c);
            }
        }
        CP_COMMIT();

        const float* Kb = smf + OFF_KB(cur);
        const float* Vb = smf + OFF_VB(cur);

        // ---- S = Q K^T (Q pre-scaled) ----
        float s[8][4];
#pragma unroll
        for (int nt = 0; nt < 8; nt++)
#pragma unroll
            for (int i = 0; i < 4; i++) s[nt][i] = 0.f;

#pragma unroll
        for (int kss = 0; kss < 8; kss++) {
            const int kb = kss * 8 + 2 * ctg;
            float2 qa0 = *reinterpret_cast<const float2*>(&smf[(qw + g) * QP + kb]);
            float2 qa1 = *reinterpret_cast<const float2*>(&smf[(qw + g + 8) * QP + kb]);
            uint32_t a[4];
            a[0] = __float_as_uint(qa0.x); a[1] = __float_as_uint(qa1.x);
            a[2] = __float_as_uint(qa0.y); a[3] = __float_as_uint(qa1.y);
#pragma unroll
            for (int nt = 0; nt < 8; nt++) {
                float2 kf = *reinterpret_cast<const float2*>(&Kb[(nt * 8 + g) * QP + kb]);
                uint32_t bb[2];
                bb[0] = __float_as_uint(kf.x); bb[1] = __float_as_uint(kf.y);
                mma_tf32(s[nt], a, bb);
            }
        }

        // ---- causal mask + online softmax (log2 domain; S pre-scaled) ----
        const bool tail = (kt >= 2 * qt);
        const int r0gl = q0 + qw + g, r1gl = r0gl + 8;
        const int kbase = kt * 64;
        float rm0 = -CUDART_INF_F, rm1 = -CUDART_INF_F;
#pragma unroll
        for (int nt = 0; nt < 8; nt++) {
            int cl = kbase + nt * 8 + 2 * ctg;
#pragma unroll
            for (int c = 0; c < 2; c++) {
                float v0 = s[nt][c];
                float v1 = s[nt][2 + c];
                if (tail) {
                    if (cl + c > r0gl) v0 = -1e30f;
                    if (cl + c > r1gl) v1 = -1e30f;
                }
                s[nt][c] = v0; s[nt][2 + c] = v1;
                rm0 = fmaxf(rm0, v0); rm1 = fmaxf(rm1, v1);
            }
        }
        rm0 = fmaxf(rm0, __shfl_xor_sync(0xffffffffu, rm0, 1));
        rm0 = fmaxf(rm0, __shfl_xor_sync(0xffffffffu, rm0, 2));
        rm1 = fmaxf(rm1, __shfl_xor_sync(0xffffffffu, rm1, 1));
        rm1 = fmaxf(rm1, __shfl_xor_sync(0xffffffffu, rm1, 2));

        float mn0 = fmaxf(mrow[0], rm0), mn1 = fmaxf(mrow[1], rm1);
        float fc0 = ex2(mrow[0] - mn0), fc1 = ex2(mrow[1] - mn1);
        float rs0 = 0.f, rs1 = 0.f;
#pragma unroll
        for (int nt = 0; nt < 8; nt++) {
#pragma unroll
            for (int c = 0; c < 2; c++) {
                float p0 = ex2(s[nt][c] - mn0);
                float p1 = ex2(s[nt][2 + c] - mn1);
                s[nt][c] = p0; s[nt][2 + c] = p1;
                rs0 += p0; rs1 += p1;
            }
        }
        rs0 += __shfl_xor_sync(0xffffffffu, rs0, 1);
        rs0 += __shfl_xor_sync(0xffffffffu, rs0, 2);
        rs1 += __shfl_xor_sync(0xffffffffu, rs1, 1);
        rs1 += __shfl_xor_sync(0xffffffffu, rs1, 2);

        lrow[0] = lrow[0] * fc0 + rs0;
        lrow[1] = lrow[1] * fc1 + rs1;
        mrow[0] = mn0; mrow[1] = mn1;
#pragma unroll
        for (int nt = 0; nt < 8; nt++) {
            o[nt][0] *= fc0; o[nt][1] *= fc0;
            o[nt][2] *= fc1; o[nt][3] *= fc1;
        }

        // ---- O += P V : LDS.128 V fragments serve ks-pairs (phi16 layout) ----
#pragma unroll
        for (int u = 0; u < 4; u++) {
            uint32_t a0[4], a1[4];
            a0[0] = __float_as_uint(s[2*u][0]);
            a0[1] = __float_as_uint(s[2*u][2]);
            a0[2] = __float_as_uint(s[2*u][1]);
            a0[3] = __float_as_uint(s[2*u][3]);
            a1[0] = __float_as_uint(s[2*u+1][0]);
            a1[1] = __float_as_uint(s[2*u+1][2]);
            a1[2] = __float_as_uint(s[2*u+1][1]);
            a1[3] = __float_as_uint(s[2*u+1][3]);
            const int kb = 16 * u + 4 * ctg;
#pragma unroll
            for (int nt = 0; nt < 8; nt++) {
                float4 vf = *reinterpret_cast<const float4*>(&Vb[(nt * 8 + g) * VP + kb]);
                uint32_t b0[2], b1[2];
                b0[0] = __float_as_uint(vf.x); b0[1] = __float_as_uint(vf.y);
                b1[0] = __float_as_uint(vf.z); b1[1] = __float_as_uint(vf.w);
                mma_tf32(o[nt], a0, b0);
                mma_tf32(o[nt], a1, b1);
            }
        }

        CP_WAIT0();
        __syncthreads();
    }

    // ---- epilogue ----
    if (!split) {
        const int limit = g_limit[b];
        const float qnan = __int_as_float(0x7FC00000);
        const int q0g = q0 + qw + g;
        const float inv0 = 1.f / lrow[0];
        const float inv1 = 1.f / lrow[1];
#pragma unroll
        for (int nt = 0; nt < 8; nt++) {
            int col = nt * 8 + 2 * ctg;
            float2 r0v, r1v;
            if (q0g >= limit) r0v = make_float2(qnan, qnan);
            else r0v = make_float2(o[nt][0] * inv0, o[nt][1] * inv0);
            if (q0g + 8 >= limit) r1v = make_float2(qnan, qnan);
            else r1v = make_float2(o[nt][2] * inv1, o[nt][3] * inv1);
            *reinterpret_cast<float2*>(&out[((size_t)b * SEQ + q0g) * HDIM + col]) = r0v;
            *reinterpret_cast<float2*>(&out[((size_t)b * SEQ + q0g + 8) * HDIM + col]) = r1v;
        }
    } else {
        const int slot = (b * 8 + (qt - 8)) * 2 + p1;
        float* po  = g_po  + (size_t)slot * 128 * 64;
        float* pml = g_pml + (size_t)slot * 256;
        const int r0l = qw + g, r1l = r0l + 8;
#pragma unroll
        for (int nt = 0; nt < 8; nt++) {
            int col = nt * 8 + 2 * ctg;
            *reinterpret_cast<float2*>(&po[r0l * 64 + col]) =
                make_float2(o[nt][0], o[nt][1]);
            *reinterpret_cast<float2*>(&po[r1l * 64 + col]) =
                make_float2(o[nt][2], o[nt][3]);
        }
        if (ctg == 0) {
            pml[r0l] = mrow[0]; pml[128 + r0l] = lrow[0];
            pml[r1l] = mrow[1]; pml[128 + r1l] = lrow[1];
        }
    }
}

// ---------------------------------------------------------------------------
// Kernel 3: combine split-K partials for qt 8..15 — massively parallel.
// grid (64, 16): x = qti*8 + rowgroup; 256 threads: one float4 per thread
// (row = rowgroup*16 + t/16, col4 = (t%16)*4). ~262K threads, no serial chains.
// ---------------------------------------------------------------------------
__global__ __launch_bounds__(256) void combine_kernel(float* __restrict__ out)
{
    const int qti = blockIdx.x >> 3;          // 0..7 -> qt = qti+8
    const int rg  = blockIdx.x & 7;           // row group of 16
    const int b   = blockIdx.y;
    const int slot0 = (b * 8 + qti) * 2;
    const float* O0  = g_po  + (size_t)slot0 * 8192;
    const float* O1  = O0 + 8192;
    const float* ml0 = g_pml + (size_t)slot0 * 256;
    const float* ml1 = ml0 + 256;

    const int t  = threadIdx.x;
    const int r  = rg * 16 + (t >> 4);
    const int c4 = (t & 15) * 4;

    const float m0 = ml0[r], l0 = ml0[128 + r];
    const float m1 = ml1[r], l1 = ml1[128 + r];
    const float mm = fmaxf(m0, m1);
    const float f0 = ex2(m0 - mm), f1 = ex2(m1 - mm);
    const float inv = 1.f / (l0 * f0 + l1 * f1);

    const int q = (qti + 8) * 128 + r;
    const int limit = g_limit[b];
    float* op = out + ((size_t)b * SEQ + q) * HDIM + c4;

    if (q >= limit) {
        const float qnan = __int_as_float(0x7FC00000);
        *reinterpret_cast<float4*>(op) = make_float4(qnan, qnan, qnan, qnan);
    } else {
        float4 a = *reinterpret_cast<const float4*>(&O0[r * 64 + c4]);
        float4 c = *reinterpret_cast<const float4*>(&O1[r * 64 + c4]);
        float4 rv;
        rv.x = (a.x * f0 + c.x * f1) * inv;
        rv.y = (a.y * f0 + c.y * f1) * inv;
        rv.z = (a.z * f0 + c.z * f1) * inv;
        rv.w = (a.w * f0 + c.w * f1) * inv;
        *reinterpret_cast<float4*>(op) = rv;
    }
}

// ---------------------------------------------------------------------------
extern "C" void kernel_launch(void* const* d_in, const int* in_sizes, int n_in,
                              void* d_out, int out_size)
{
    const float* x  = (const float*)d_in[0];
    const float* Wk = (const float*)d_in[1];
    const float* Wq = (const float*)d_in[2];
    const float* Wv = (const float*)d_in[3];
    const int*  idx = (const int*)d_in[4];
    float* out = (float*)d_out;

    (void)in_sizes; (void)n_in; (void)out_size;

    cudaFuncSetAttribute(attn_kernel,
                         cudaFuncAttributeMaxDynamicSharedMemorySize,
                         ATTN_SMEM_BYTES);

    prep_kernel<<<64, 256>>>(Wk, Wq, Wv, idx);
    proj_kernel<<<ROWS_TOTAL / 64, 256>>>(x);
    attn_kernel<<<dim3(BATCH, 24), 256, ATTN_SMEM_BYTES>>>(out);
    combine_kernel<<<dim3(64, BATCH), 256>>>(out);
}

// round 15
// speedup vs baseline: 1.1955x; 1.1213x over previous
#include <cuda_runtime.h>
#include <cuda_bf16.h>
#include <math_constants.h>
#include <cstdint>

// Problem shape (fixed): B=16, T=2048, C=512, H=64
#define BATCH 16
#define SEQ   2048
#define CDIM  512
#define HDIM  64
#define END_TOKEN 32000

#define ROWS_TOTAL (BATCH * SEQ)          // 32768
#define SCALE 0.04419417382415922f        // 512^-0.5
#define SCL2  0.06377946286456401f        // SCALE * log2(e)

__device__ __forceinline__ float tf32r(float x) {
    float y; asm("cvt.rna.tf32.f32 %0,%1;" : "=f"(y) : "f"(x)); return y;
}
__device__ __forceinline__ float ex2(float x) {
    float y; asm("ex2.approx.f32 %0,%1;" : "=f"(y) : "f"(x)); return y;
}
__device__ __forceinline__ uint32_t smem_u32(const void* p) {
    uint32_t a;
    asm("{ .reg .u64 t; cvta.to.shared.u64 t, %1; cvt.u32.u64 %0, t; }"
        : "=r"(a) : "l"(p));
    return a;
}
__device__ __forceinline__ void cp16(uint32_t dst, const void* src) {
    asm volatile("cp.async.cg.shared.global [%0], [%1], 16;"
                 :: "r"(dst), "l"(src) : "memory");
}
#define CP_COMMIT() asm volatile("cp.async.commit_group;" ::: "memory")
#define CP_WAIT0()  asm volatile("cp.async.wait_group 0;" ::: "memory")

// pair-permutation within 8: logical i -> physical (puts (i, i+4) adjacent)
__device__ __forceinline__ int perm8(int i) {
    return (i & ~7) | ((i & 3) << 1) | ((i >> 2) & 1);
}

// m16n8k8 tf32 mma (sm_80 portable feature -> fallback HMMA on sm_103)
__device__ __forceinline__ void mma_tf32(float* d, const uint32_t* a, const uint32_t* b) {
    asm volatile(
        "mma.sync.aligned.m16n8k8.row.col.f32.tf32.tf32.f32 "
        "{%0,%1,%2,%3}, {%4,%5,%6,%7}, {%8,%9}, {%0,%1,%2,%3};"
        : "+f"(d[0]), "+f"(d[1]), "+f"(d[2]), "+f"(d[3])
        : "r"(a[0]), "r"(a[1]), "r"(a[2]), "r"(a[3]), "r"(b[0]), "r"(b[1]));
}

// Scratch (allocation-free rule: __device__ globals)
// g_q: [row][perm8(h)] tf32(q*SCL2).  g_k: [row][perm8(h)] tf32.
// g_vt: [b][h][phi16(t)] tf32 (t interleaved within 16-blocks for LDS.128).
__device__ float g_q[ROWS_TOTAL * HDIM];
__device__ float g_k[ROWS_TOTAL * HDIM];
__device__ float g_vt[BATCH * HDIM * SEQ];
__device__ float g_wt[3 * HDIM * CDIM];   // W^T tf32: [mat][n][perm8(k)]
__device__ int   g_limit[BATCH];
// split-K partial results: 16 b x 8 heavy qt x 2 pieces
__device__ float g_po[BATCH * 8 * 2 * 128 * 64];   // unnormalized O
__device__ float g_pml[BATCH * 8 * 2 * 256];       // m[128] | l[128]

// Piece table (heavy-first). qt<8: single direct piece. qt>=8: two pieces.
__device__ const int PQT[24] = {7,8,9,10,11,12,13,14,15,15, 6,14, 5,13,
                                4,12, 3,11, 2,10, 1,9, 0,8};
__device__ const int PP1[24] = {0,0,0,0,0,0,0,0,0,1, 0,1, 0,1,
                                0,1, 0,1, 0,1, 0,1, 0,1};   // is piece1

// ---------------------------------------------------------------------------
// Kernel 0 (merged): blocks 0..47 transpose W (perm8 on k, tf32-rounded);
// blocks 48..63 run the end-token scan (faithful; never fires here).
// ---------------------------------------------------------------------------
__global__ void prep_kernel(const float* __restrict__ Wk,
                            const float* __restrict__ Wq,
                            const float* __restrict__ Wv,
                            const int* __restrict__ idx)
{
    if (blockIdx.x < 48) {
        const int m  = blockIdx.x / 16;
        const int ks = blockIdx.x % 16;           // k-slice of 32
        const float* src = (m == 0) ? Wq : (m == 1) ? Wk : Wv;
        float* dst = g_wt + (size_t)m * HDIM * CDIM;
        for (int i = threadIdx.x; i < 32 * 64; i += 256) {
            int k = ks * 32 + (i >> 6);
            int n = i & 63;
            dst[(size_t)n * CDIM + perm8(k)] = tf32r(src[(size_t)k * HDIM + n]);
        }
    } else {
        __shared__ int best;
        if (threadIdx.x == 0) best = SEQ;
        __syncthreads();
        const int b = blockIdx.x - 48;
        for (int t = threadIdx.x; t < SEQ; t += blockDim.x)
            if (idx[(size_t)b * SEQ + t] == END_TOKEN) atomicMin(&best, t);
        __syncthreads();
        if (threadIdx.x == 0) g_limit[b] = best;
    }
}

// ---------------------------------------------------------------------------
// Kernel 1: QKV projection via tf32 mma.sync (64 rows x 192 cols per CTA).
// Double-buffered smem: B staged by cp.async (pre-rounded g_wt), A staged via
// registers (tf32r hook). ONE __syncthreads per chunk.
// smem: 2 x (A[64][40] + B[192][40]) = 81,920 B dynamic -> 2 CTAs/SM.
// ---------------------------------------------------------------------------
#define PJP 40
#define PJ_A(buf) ((buf) * 2560)                 // 64*40 floats each
#define PJ_B(buf) (5120 + (buf) * 7680)          // 192*40 floats each
#define PJ_SMEM_FLOATS 20480
#define PJ_SMEM_BYTES (PJ_SMEM_FLOATS * 4)

__global__ __launch_bounds__(256, 2) void proj_kernel(const float* __restrict__ x)
{
    extern __shared__ float sbuf[];
    const uint32_t smb = smem_u32(sbuf);

    const int t    = threadIdx.x;
    const int wid  = t >> 5;
    const int lane = t & 31;
    const int g    = lane >> 2;
    const int ctg  = lane & 3;
    const int wm   = wid >> 2;
    const int wn   = wid & 3;
    const int row0 = blockIdx.x * 64;

    // staging coordinates
    const int ar = t >> 2, af = (t & 3) * 8;             // A: row, 8 cols
    const int bn = t >> 3, bf4 = (t & 7) * 4;            // B: 6 cp.async/thread

    float acc[2][6][4];
#pragma unroll
    for (int mt = 0; mt < 2; mt++)
#pragma unroll
        for (int nt = 0; nt < 6; nt++)
#pragma unroll
            for (int i = 0; i < 4; i++) acc[mt][nt][i] = 0.f;

    // prologue: cp.async B chunk0 -> buf0; load x chunk0 into regs
    {
#pragma unroll
        for (int j = 0; j < 6; j++) {
            int n = bn + 32 * j;
            cp16(smb + (uint32_t)(PJ_B(0) + n * PJP + bf4) * 4,
                 g_wt + (size_t)n * CDIM + bf4);
        }
        CP_COMMIT();
    }
    float4 pa0, pa1;
    {
        const float* xp = x + (size_t)(row0 + ar) * CDIM + af;
        pa0 = *reinterpret_cast<const float4*>(xp);
        pa1 = *reinterpret_cast<const float4*>(xp + 4);
    }

    for (int kc = 0; kc < 16; kc++) {
        const int buf = kc & 1;

        // store A chunk (tf32-rounded, perm8 pairs via STS.64)
        {
            float* a = &sbuf[PJ_A(buf) + ar * PJP + af];
            *reinterpret_cast<float2*>(&a[0]) = make_float2(tf32r(pa0.x), tf32r(pa1.x));
            *reinterpret_cast<float2*>(&a[2]) = make_float2(tf32r(pa0.y), tf32r(pa1.y));
            *reinterpret_cast<float2*>(&a[4]) = make_float2(tf32r(pa0.z), tf32r(pa1.z));
            *reinterpret_cast<float2*>(&a[6]) = make_float2(tf32r(pa0.w), tf32r(pa1.w));
        }
        CP_WAIT0();            // B(kc) landed (only outstanding group)
        __syncthreads();       // all stores/cp.async of chunk kc visible

        // issue B(kc+1) into the other buffer (safe: all warps are past
        // MMA(kc-1), the last reader of that buffer) + prefetch x(kc+1)
        if (kc < 15) {
            const int ko = (kc + 1) * 32;
#pragma unroll
            for (int j = 0; j < 6; j++) {
                int n = bn + 32 * j;
                cp16(smb + (uint32_t)(PJ_B(buf ^ 1) + n * PJP + bf4) * 4,
                     g_wt + (size_t)n * CDIM + ko + bf4);
            }
            CP_COMMIT();
            const float* xp = x + (size_t)(row0 + ar) * CDIM + ko + af;
            pa0 = *reinterpret_cast<const float4*>(xp);
            pa1 = *reinterpret_cast<const float4*>(xp + 4);
        }

        // MMAs on chunk kc
        const float* As = sbuf + PJ_A(buf);
        const float* Bs = sbuf + PJ_B(buf);
#pragma unroll
        for (int ks = 0; ks < 4; ks++) {
            const int kb = ks * 8 + 2 * ctg;
            uint32_t a[2][4];
#pragma unroll
            for (int mt = 0; mt < 2; mt++) {
                int row = wm * 32 + mt * 16;
                float2 f0 = *reinterpret_cast<const float2*>(&As[(row + g) * PJP + kb]);
                float2 f1 = *reinterpret_cast<const float2*>(&As[(row + g + 8) * PJP + kb]);
                a[mt][0] = __float_as_uint(f0.x); a[mt][1] = __float_as_uint(f1.x);
                a[mt][2] = __float_as_uint(f0.y); a[mt][3] = __float_as_uint(f1.y);
            }
#pragma unroll
            for (int nt = 0; nt < 6; nt++) {
                int n = wn * 48 + nt * 8;
                float2 bf = *reinterpret_cast<const float2*>(&Bs[(n + g) * PJP + kb]);
                uint32_t b[2];
                b[0] = __float_as_uint(bf.x); b[1] = __float_as_uint(bf.y);
                mma_tf32(acc[0][nt], a[0], b);
                mma_tf32(acc[1][nt], a[1], b);
            }
        }
    }
    __syncthreads();   // all MMAs done before smem reuse as Vtr

    // ---- epilogue (unchanged from R14) ----
    float* Vtr = sbuf;    // [64][68] reuse
#pragma unroll
    for (int mt = 0; mt < 2; mt++) {
#pragma unroll
        for (int nt = 0; nt < 6; nt++) {
            int col = wn * 48 + nt * 8 + 2 * ctg;
            int mat = col >> 6, c0 = col & 63;
            int r0 = row0 + wm * 32 + mt * 16 + g;
            if (mat == 0) {   // Q: pre-scale by SCL2, perm8 on h
                g_q[(size_t)r0 * HDIM + perm8(c0)]           = tf32r(acc[mt][nt][0] * SCL2);
                g_q[(size_t)r0 * HDIM + perm8(c0 + 1)]       = tf32r(acc[mt][nt][1] * SCL2);
                g_q[(size_t)(r0 + 8) * HDIM + perm8(c0)]     = tf32r(acc[mt][nt][2] * SCL2);
                g_q[(size_t)(r0 + 8) * HDIM + perm8(c0 + 1)] = tf32r(acc[mt][nt][3] * SCL2);
            } else if (mat == 1) {   // K: perm8 on h
                g_k[(size_t)r0 * HDIM + perm8(c0)]           = tf32r(acc[mt][nt][0]);
                g_k[(size_t)r0 * HDIM + perm8(c0 + 1)]       = tf32r(acc[mt][nt][1]);
                g_k[(size_t)(r0 + 8) * HDIM + perm8(c0)]     = tf32r(acc[mt][nt][2]);
                g_k[(size_t)(r0 + 8) * HDIM + perm8(c0 + 1)] = tf32r(acc[mt][nt][3]);
            } else {   // V: phi16 interleave on t
                int tl  = wm * 32 + mt * 16 + g;
                int tlp = (tl & ~15) + 4 * (g >> 1) + (g & 1);   // phi16(tl)
                Vtr[c0 * 68 + tlp]             = tf32r(acc[mt][nt][0]);
                Vtr[(c0 + 1) * 68 + tlp]       = tf32r(acc[mt][nt][1]);
                Vtr[c0 * 68 + tlp + 2]         = tf32r(acc[mt][nt][2]);  // phi16(tl+8)
                Vtr[(c0 + 1) * 68 + tlp + 2]   = tf32r(acc[mt][nt][3]);
            }
        }
    }
    __syncthreads();

    {
        const int b  = row0 >> 11;
        const int t0 = row0 & 2047;
#pragma unroll
        for (int i = 0; i < 4; i++) {
            int idx = t + 256 * i;
            int h = idx >> 4, c = (idx & 15) * 4;
            float4 v = *reinterpret_cast<const float4*>(&Vtr[h * 68 + c]);
            *reinterpret_cast<float4*>(
                &g_vt[((size_t)b * HDIM + h) * SEQ + t0 + c]) = v;
        }
    }
}

// ---------------------------------------------------------------------------
// Kernel 2: causal flash attention, split-K pieces (unchanged — validated R12).
// ---------------------------------------------------------------------------
#define QP 72
#define VP 80
#define OFF_KB(buf) (128 * QP + (buf) * 64 * QP)
#define OFF_VB(buf) (128 * QP + 2 * 64 * QP + (buf) * 64 * VP)
#define ATTN_SMEM_FLOATS (128 * QP + 2 * 64 * QP + 2 * 64 * VP)
#define ATTN_SMEM_BYTES (ATTN_SMEM_FLOATS * 4)

__global__ __launch_bounds__(256, 2) void attn_kernel(float* __restrict__ out)
{
    extern __shared__ float smf[];
    const uint32_t smb = smem_u32(smf);

    const int t    = threadIdx.x;
    const int wid  = t >> 5;
    const int lane = t & 31;
    const int g    = lane >> 2;
    const int ctg  = lane & 3;
    const int qw   = wid * 16;
    const int b    = blockIdx.x;
    const int pc   = blockIdx.y;
    const int qt   = PQT[pc];
    const int p1   = PP1[pc];
    const bool split = (qt >= 8);
    const int ks   = p1 ? 16 : 0;
    const int ke   = (split && !p1) ? 16 : (2 * qt + 2);
    const int q0   = qt * 128;

    const float* kg0 = g_k  + ((size_t)b * SEQ) * HDIM;
    const float* vg0 = g_vt + ((size_t)b * HDIM) * SEQ;

    // stage Q
    {
        const float* qg = g_q + ((size_t)b * SEQ + q0) * HDIM;
#pragma unroll
        for (int i = 0; i < 8; i++) {
            int idx = t + 256 * i;
            int r = idx >> 4, c = (idx & 15) * 4;
            cp16(smb + (uint32_t)(r * QP + c) * 4, qg + (size_t)r * HDIM + c);
        }
    }
    // stage K/V block ks into buf 0
    {
        const float* kg = kg0 + (size_t)ks * 64 * HDIM;
        const float* vg = vg0 + (size_t)ks * 64;
#pragma unroll
        for (int i = 0; i < 4; i++) {
            int idx = t + 256 * i;
            int r = idx >> 4, c = (idx & 15) * 4;
            cp16(smb + (uint32_t)(OFF_KB(0) + r * QP + c) * 4,
                 kg + (size_t)r * HDIM + c);
            cp16(smb + (uint32_t)(OFF_VB(0) + r * VP + c) * 4,
                 vg + (size_t)r * SEQ + c);
        }
    }
    CP_COMMIT(); CP_WAIT0(); __syncthreads();

    float mrow[2] = { -CUDART_INF_F, -CUDART_INF_F };   // log2 domain
    float lrow[2] = { 0.f, 0.f };
    float o[8][4];
#pragma unroll
    for (int nt = 0; nt < 8; nt++)
#pragma unroll
        for (int i = 0; i < 4; i++) o[nt][i] = 0.f;

    for (int kt = ks; kt < ke; kt++) {
        const int cur = (kt - ks) & 1;

        if (kt + 1 < ke) {
            const float* kg = kg0 + (size_t)(kt + 1) * 64 * HDIM;
            const float* vg = vg0 + (size_t)(kt + 1) * 64;
#pragma unroll
            for (int i = 0; i < 4; i++) {
                int idx = t + 256 * i;
                int r = idx >> 4, c = (idx & 15) * 4;
                cp16(smb + (uint32_t)(OFF_KB(cur ^ 1) + r * QP + c) * 4,
                     kg + (size_t)r * HDIM + c);
                cp16(smb + (uint32_t)(OFF_VB(cur ^ 1) + r * VP + c) * 4,
                     vg + (size_t)r * SEQ + c);
            }
        }
        CP_COMMIT();

        const float* Kb = smf + OFF_KB(cur);
        const float* Vb = smf + OFF_VB(cur);

        // ---- S = Q K^T (Q pre-scaled) ----
        float s[8][4];
#pragma unroll
        for (int nt = 0; nt < 8; nt++)
#pragma unroll
            for (int i = 0; i < 4; i++) s[nt][i] = 0.f;

#pragma unroll
        for (int kss = 0; kss < 8; kss++) {
            const int kb = kss * 8 + 2 * ctg;
            float2 qa0 = *reinterpret_cast<const float2*>(&smf[(qw + g) * QP + kb]);
            float2 qa1 = *reinterpret_cast<const float2*>(&smf[(qw + g + 8) * QP + kb]);
            uint32_t a[4];
            a[0] = __float_as_uint(qa0.x); a[1] = __float_as_uint(qa1.x);
            a[2] = __float_as_uint(qa0.y); a[3] = __float_as_uint(qa1.y);
#pragma unroll
            for (int nt = 0; nt < 8; nt++) {
                float2 kf = *reinterpret_cast<const float2*>(&Kb[(nt * 8 + g) * QP + kb]);
                uint32_t bb[2];
                bb[0] = __float_as_uint(kf.x); bb[1] = __float_as_uint(kf.y);
                mma_tf32(s[nt], a, bb);
            }
        }

        // ---- causal mask + online softmax (log2 domain; S pre-scaled) ----
        const bool tail = (kt >= 2 * qt);
        const int r0gl = q0 + qw + g, r1gl = r0gl + 8;
        const int kbase = kt * 64;
        float rm0 = -CUDART_INF_F, rm1 = -CUDART_INF_F;
#pragma unroll
        for (int nt = 0; nt < 8; nt++) {
            int cl = kbase + nt * 8 + 2 * ctg;
#pragma unroll
            for (int c = 0; c < 2; c++) {
                float v0 = s[nt][c];
                float v1 = s[nt][2 + c];
                if (tail) {
                    if (cl + c > r0gl) v0 = -1e30f;
                    if (cl + c > r1gl) v1 = -1e30f;
                }
                s[nt][c] = v0; s[nt][2 + c] = v1;
                rm0 = fmaxf(rm0, v0); rm1 = fmaxf(rm1, v1);
            }
        }
        rm0 = fmaxf(rm0, __shfl_xor_sync(0xffffffffu, rm0, 1));
        rm0 = fmaxf(rm0, __shfl_xor_sync(0xffffffffu, rm0, 2));
        rm1 = fmaxf(rm1, __shfl_xor_sync(0xffffffffu, rm1, 1));
        rm1 = fmaxf(rm1, __shfl_xor_sync(0xffffffffu, rm1, 2));

        float mn0 = fmaxf(mrow[0], rm0), mn1 = fmaxf(mrow[1], rm1);
        float fc0 = ex2(mrow[0] - mn0), fc1 = ex2(mrow[1] - mn1);
        float rs0 = 0.f, rs1 = 0.f;
#pragma unroll
        for (int nt = 0; nt < 8; nt++) {
#pragma unroll
            for (int c = 0; c < 2; c++) {
                float p0 = ex2(s[nt][c] - mn0);
                float p1 = ex2(s[nt][2 + c] - mn1);
                s[nt][c] = p0; s[nt][2 + c] = p1;
                rs0 += p0; rs1 += p1;
            }
        }
        rs0 += __shfl_xor_sync(0xffffffffu, rs0, 1);
        rs0 += __shfl_xor_sync(0xffffffffu, rs0, 2);
        rs1 += __shfl_xor_sync(0xffffffffu, rs1, 1);
        rs1 += __shfl_xor_sync(0xffffffffu, rs1, 2);

        lrow[0] = lrow[0] * fc0 + rs0;
        lrow[1] = lrow[1] * fc1 + rs1;
        mrow[0] = mn0; mrow[1] = mn1;
#pragma unroll
        for (int nt = 0; nt < 8; nt++) {
            o[nt][0] *= fc0; o[nt][1] *= fc0;
            o[nt][2] *= fc1; o[nt][3] *= fc1;
        }

        // ---- O += P V : LDS.128 V fragments serve ks-pairs (phi16 layout) ----
#pragma unroll
        for (int u = 0; u < 4; u++) {
            uint32_t a0[4], a1[4];
            a0[0] = __float_as_uint(s[2*u][0]);
            a0[1] = __float_as_uint(s[2*u][2]);
            a0[2] = __float_as_uint(s[2*u][1]);
            a0[3] = __float_as_uint(s[2*u][3]);
            a1[0] = __float_as_uint(s[2*u+1][0]);
            a1[1] = __float_as_uint(s[2*u+1][2]);
            a1[2] = __float_as_uint(s[2*u+1][1]);
            a1[3] = __float_as_uint(s[2*u+1][3]);
            const int kb = 16 * u + 4 * ctg;
#pragma unroll
            for (int nt = 0; nt < 8; nt++) {
                float4 vf = *reinterpret_cast<const float4*>(&Vb[(nt * 8 + g) * VP + kb]);
                uint32_t b0[2], b1[2];
                b0[0] = __float_as_uint(vf.x); b0[1] = __float_as_uint(vf.y);
                b1[0] = __float_as_uint(vf.z); b1[1] = __float_as_uint(vf.w);
                mma_tf32(o[nt], a0, b0);
                mma_tf32(o[nt], a1, b1);
            }
        }

        CP_WAIT0();
        __syncthreads();
    }

    // ---- epilogue ----
    if (!split) {
        const int limit = g_limit[b];
        const float qnan = __int_as_float(0x7FC00000);
        const int q0g = q0 + qw + g;
        const float inv0 = 1.f / lrow[0];
        const float inv1 = 1.f / lrow[1];
#pragma unroll
        for (int nt = 0; nt < 8; nt++) {
            int col = nt * 8 + 2 * ctg;
            float2 r0v, r1v;
            if (q0g >= limit) r0v = make_float2(qnan, qnan);
            else r0v = make_float2(o[nt][0] * inv0, o[nt][1] * inv0);
            if (q0g + 8 >= limit) r1v = make_float2(qnan, qnan);
            else r1v = make_float2(o[nt][2] * inv1, o[nt][3] * inv1);
            *reinterpret_cast<float2*>(&out[((size_t)b * SEQ + q0g) * HDIM + col]) = r0v;
            *reinterpret_cast<float2*>(&out[((size_t)b * SEQ + q0g + 8) * HDIM + col]) = r1v;
        }
    } else {
        const int slot = (b * 8 + (qt - 8)) * 2 + p1;
        float* po  = g_po  + (size_t)slot * 128 * 64;
        float* pml = g_pml + (size_t)slot * 256;
        const int r0l = qw + g, r1l = r0l + 8;
#pragma unroll
        for (int nt = 0; nt < 8; nt++) {
            int col = nt * 8 + 2 * ctg;
            *reinterpret_cast<float2*>(&po[r0l * 64 + col]) =
                make_float2(o[nt][0], o[nt][1]);
            *reinterpret_cast<float2*>(&po[r1l * 64 + col]) =
                make_float2(o[nt][2], o[nt][3]);
        }
        if (ctg == 0) {
            pml[r0l] = mrow[0]; pml[128 + r0l] = lrow[0];
            pml[r1l] = mrow[1]; pml[128 + r1l] = lrow[1];
        }
    }
}

// ---------------------------------------------------------------------------
// Kernel 3: combine split-K partials for qt 8..15 — massively parallel.
// (unchanged — validated R14)
// ---------------------------------------------------------------------------
__global__ __launch_bounds__(256) void combine_kernel(float* __restrict__ out)
{
    const int qti = blockIdx.x >> 3;          // 0..7 -> qt = qti+8
    const int rg  = blockIdx.x & 7;           // row group of 16
    const int b   = blockIdx.y;
    const int slot0 = (b * 8 + qti) * 2;
    const float* O0  = g_po  + (size_t)slot0 * 8192;
    const float* O1  = O0 + 8192;
    const float* ml0 = g_pml + (size_t)slot0 * 256;
    const float* ml1 = ml0 + 256;

    const int t  = threadIdx.x;
    const int r  = rg * 16 + (t >> 4);
    const int c4 = (t & 15) * 4;

    const float m0 = ml0[r], l0 = ml0[128 + r];
    const float m1 = ml1[r], l1 = ml1[128 + r];
    const float mm = fmaxf(m0, m1);
    const float f0 = ex2(m0 - mm), f1 = ex2(m1 - mm);
    const float inv = 1.f / (l0 * f0 + l1 * f1);

    const int q = (qti + 8) * 128 + r;
    const int limit = g_limit[b];
    float* op = out + ((size_t)b * SEQ + q) * HDIM + c4;

    if (q >= limit) {
        const float qnan = __int_as_float(0x7FC00000);
        *reinterpret_cast<float4*>(op) = make_float4(qnan, qnan, qnan, qnan);
    } else {
        float4 a = *reinterpret_cast<const float4*>(&O0[r * 64 + c4]);
        float4 c = *reinterpret_cast<const float4*>(&O1[r * 64 + c4]);
        float4 rv;
        rv.x = (a.x * f0 + c.x * f1) * inv;
        rv.y = (a.y * f0 + c.y * f1) * inv;
        rv.z = (a.z * f0 + c.z * f1) * inv;
        rv.w = (a.w * f0 + c.w * f1) * inv;
        *reinterpret_cast<float4*>(op) = rv;
    }
}

// ---------------------------------------------------------------------------
extern "C" void kernel_launch(void* const* d_in, const int* in_sizes, int n_in,
                              void* d_out, int out_size)
{
    const float* x  = (const float*)d_in[0];
    const float* Wk = (const float*)d_in[1];
    const float* Wq = (const float*)d_in[2];
    const float* Wv = (const float*)d_in[3];
    const int*  idx = (const int*)d_in[4];
    float* out = (float*)d_out;

    (void)in_sizes; (void)n_in; (void)out_size;

    cudaFuncSetAttribute(proj_kernel,
                         cudaFuncAttributeMaxDynamicSharedMemorySize,
                         PJ_SMEM_BYTES);
    cudaFuncSetAttribute(attn_kernel,
                         cudaFuncAttributeMaxDynamicSharedMemorySize,
                         ATTN_SMEM_BYTES);

    prep_kernel<<<64, 256>>>(Wk, Wq, Wv, idx);
    proj_kernel<<<ROWS_TOTAL / 64, 256, PJ_SMEM_BYTES>>>(x);
    attn_kernel<<<dim3(BATCH, 24), 256, ATTN_SMEM_BYTES>>>(out);
    combine_kernel<<<dim3(64, BATCH), 256>>>(out);
}

// round 16
// speedup vs baseline: 1.2393x; 1.0367x over previous
#include <cuda_runtime.h>
#include <cuda_bf16.h>
#include <math_constants.h>
#include <cstdint>

// Problem shape (fixed): B=16, T=2048, C=512, H=64
#define BATCH 16
#define SEQ   2048
#define CDIM  512
#define HDIM  64
#define END_TOKEN 32000

#define ROWS_TOTAL (BATCH * SEQ)          // 32768
#define SCALE 0.04419417382415922f        // 512^-0.5
#define SCL2  0.06377946286456401f        // SCALE * log2(e)

__device__ __forceinline__ float tf32r(float x) {
    float y; asm("cvt.rna.tf32.f32 %0,%1;" : "=f"(y) : "f"(x)); return y;
}
__device__ __forceinline__ float ex2(float x) {
    float y; asm("ex2.approx.f32 %0,%1;" : "=f"(y) : "f"(x)); return y;
}
__device__ __forceinline__ uint32_t smem_u32(const void* p) {
    uint32_t a;
    asm("{ .reg .u64 t; cvta.to.shared.u64 t, %1; cvt.u32.u64 %0, t; }"
        : "=r"(a) : "l"(p));
    return a;
}
__device__ __forceinline__ void cp16(uint32_t dst, const void* src) {
    asm volatile("cp.async.cg.shared.global [%0], [%1], 16;"
                 :: "r"(dst), "l"(src) : "memory");
}
#define CP_COMMIT() asm volatile("cp.async.commit_group;" ::: "memory")
#define CP_WAIT0()  asm volatile("cp.async.wait_group 0;" ::: "memory")

// pair-permutation within 8: logical i -> physical (puts (i, i+4) adjacent)
__device__ __forceinline__ int perm8(int i) {
    return (i & ~7) | ((i & 3) << 1) | ((i >> 2) & 1);
}

// m16n8k8 tf32 mma (sm_80 portable feature -> fallback HMMA on sm_103)
__device__ __forceinline__ void mma_tf32(float* d, const uint32_t* a, const uint32_t* b) {
    asm volatile(
        "mma.sync.aligned.m16n8k8.row.col.f32.tf32.tf32.f32 "
        "{%0,%1,%2,%3}, {%4,%5,%6,%7}, {%8,%9}, {%0,%1,%2,%3};"
        : "+f"(d[0]), "+f"(d[1]), "+f"(d[2]), "+f"(d[3])
        : "r"(a[0]), "r"(a[1]), "r"(a[2]), "r"(a[3]), "r"(b[0]), "r"(b[1]));
}

// Scratch (allocation-free rule: __device__ globals)
// g_q: [row][perm8(h)] tf32(q*SCL2).  g_k: [row][perm8(h)] tf32.
// g_vt: [b][h][phi16(t)] tf32 (t interleaved within 16-blocks for LDS.128).
__device__ float g_q[ROWS_TOTAL * HDIM];
__device__ float g_k[ROWS_TOTAL * HDIM];
__device__ float g_vt[BATCH * HDIM * SEQ];
__device__ float g_wt[3 * HDIM * CDIM];   // W^T tf32: [mat][n][perm8(k)]
__device__ int   g_nlim[BATCH];           // SEQ - first_end (atomicMax; 0 = none)
// split-K partial results: 16 b x 8 heavy qt x 2 pieces
__device__ float g_po[BATCH * 8 * 2 * 128 * 64];   // unnormalized O
__device__ float g_pml[BATCH * 8 * 2 * 256];       // m[128] | l[128]

// Piece table (heavy-first). qt<8: single direct piece. qt>=8: two pieces.
__device__ const int PQT[24] = {7,8,9,10,11,12,13,14,15,15, 6,14, 5,13,
                                4,12, 3,11, 2,10, 1,9, 0,8};
__device__ const int PP1[24] = {0,0,0,0,0,0,0,0,0,1, 0,1, 0,1,
                                0,1, 0,1, 0,1, 0,1, 0,1};   // is piece1

// ---------------------------------------------------------------------------
// Kernel 0 (merged): blocks 0..47 transpose W (perm8 on k, tf32-rounded,
// k-fast thread mapping -> coalesced 128B writes); blocks 48..175 scan idx
// (1 element/thread; atomicMax on g_nlim, idempotent across graph replays).
// ---------------------------------------------------------------------------
__global__ void prep_kernel(const float* __restrict__ Wk,
                            const float* __restrict__ Wq,
                            const float* __restrict__ Wv,
                            const int* __restrict__ idx)
{
    if (blockIdx.x < 48) {
        const int m  = blockIdx.x / 16;
        const int ks = blockIdx.x % 16;           // k-slice of 32
        const float* src = (m == 0) ? Wq : (m == 1) ? Wk : Wv;
        float* dst = g_wt + (size_t)m * HDIM * CDIM;
        for (int i = threadIdx.x; i < 32 * 64; i += 256) {
            int k = ks * 32 + (i & 31);           // k fast -> coalesced writes
            int n = i >> 5;
            dst[(size_t)n * CDIM + perm8(k)] = tf32r(src[(size_t)k * HDIM + n]);
        }
    } else {
        const int blk = blockIdx.x - 48;          // 0..127
        const int b   = blk >> 3;
        const int seg = blk & 7;
        const int t0  = seg * 256 + threadIdx.x;
        if (idx[(size_t)b * SEQ + t0] == END_TOKEN)
            atomicMax(&g_nlim[b], SEQ - t0);
    }
}

// ---------------------------------------------------------------------------
// Kernel 1: QKV projection via tf32 mma.sync (64 rows x 192 cols per CTA).
// (unchanged — validated R15 pipeline)
// ---------------------------------------------------------------------------
#define PJP 40
#define PJ_A(buf) ((buf) * 2560)                 // 64*40 floats each
#define PJ_B(buf) (5120 + (buf) * 7680)          // 192*40 floats each
#define PJ_SMEM_FLOATS 20480
#define PJ_SMEM_BYTES (PJ_SMEM_FLOATS * 4)

__global__ __launch_bounds__(256, 2) void proj_kernel(const float* __restrict__ x)
{
    extern __shared__ float sbuf[];
    const uint32_t smb = smem_u32(sbuf);

    const int t    = threadIdx.x;
    const int wid  = t >> 5;
    const int lane = t & 31;
    const int g    = lane >> 2;
    const int ctg  = lane & 3;
    const int wm   = wid >> 2;
    const int wn   = wid & 3;
    const int row0 = blockIdx.x * 64;

    const int ar = t >> 2, af = (t & 3) * 8;             // A: row, 8 cols
    const int bn = t >> 3, bf4 = (t & 7) * 4;            // B: 6 cp.async/thread

    float acc[2][6][4];
#pragma unroll
    for (int mt = 0; mt < 2; mt++)
#pragma unroll
        for (int nt = 0; nt < 6; nt++)
#pragma unroll
            for (int i = 0; i < 4; i++) acc[mt][nt][i] = 0.f;

    {
#pragma unroll
        for (int j = 0; j < 6; j++) {
            int n = bn + 32 * j;
            cp16(smb + (uint32_t)(PJ_B(0) + n * PJP + bf4) * 4,
                 g_wt + (size_t)n * CDIM + bf4);
        }
        CP_COMMIT();
    }
    float4 pa0, pa1;
    {
        const float* xp = x + (size_t)(row0 + ar) * CDIM + af;
        pa0 = *reinterpret_cast<const float4*>(xp);
        pa1 = *reinterpret_cast<const float4*>(xp + 4);
    }

    for (int kc = 0; kc < 16; kc++) {
        const int buf = kc & 1;

        {
            float* a = &sbuf[PJ_A(buf) + ar * PJP + af];
            *reinterpret_cast<float2*>(&a[0]) = make_float2(tf32r(pa0.x), tf32r(pa1.x));
            *reinterpret_cast<float2*>(&a[2]) = make_float2(tf32r(pa0.y), tf32r(pa1.y));
            *reinterpret_cast<float2*>(&a[4]) = make_float2(tf32r(pa0.z), tf32r(pa1.z));
            *reinterpret_cast<float2*>(&a[6]) = make_float2(tf32r(pa0.w), tf32r(pa1.w));
        }
        CP_WAIT0();
        __syncthreads();

        if (kc < 15) {
            const int ko = (kc + 1) * 32;
#pragma unroll
            for (int j = 0; j < 6; j++) {
                int n = bn + 32 * j;
                cp16(smb + (uint32_t)(PJ_B(buf ^ 1) + n * PJP + bf4) * 4,
                     g_wt + (size_t)n * CDIM + ko + bf4);
            }
            CP_COMMIT();
            const float* xp = x + (size_t)(row0 + ar) * CDIM + ko + af;
            pa0 = *reinterpret_cast<const float4*>(xp);
            pa1 = *reinterpret_cast<const float4*>(xp + 4);
        }

        const float* As = sbuf + PJ_A(buf);
        const float* Bs = sbuf + PJ_B(buf);
#pragma unroll
        for (int ks = 0; ks < 4; ks++) {
            const int kb = ks * 8 + 2 * ctg;
            uint32_t a[2][4];
#pragma unroll
            for (int mt = 0; mt < 2; mt++) {
                int row = wm * 32 + mt * 16;
                float2 f0 = *reinterpret_cast<const float2*>(&As[(row + g) * PJP + kb]);
                float2 f1 = *reinterpret_cast<const float2*>(&As[(row + g + 8) * PJP + kb]);
                a[mt][0] = __float_as_uint(f0.x); a[mt][1] = __float_as_uint(f1.x);
                a[mt][2] = __float_as_uint(f0.y); a[mt][3] = __float_as_uint(f1.y);
            }
#pragma unroll
            for (int nt = 0; nt < 6; nt++) {
                int n = wn * 48 + nt * 8;
                float2 bf = *reinterpret_cast<const float2*>(&Bs[(n + g) * PJP + kb]);
                uint32_t b[2];
                b[0] = __float_as_uint(bf.x); b[1] = __float_as_uint(bf.y);
                mma_tf32(acc[0][nt], a[0], b);
                mma_tf32(acc[1][nt], a[1], b);
            }
        }
    }
    __syncthreads();   // all MMAs done before smem reuse as Vtr

    // ---- epilogue (unchanged) ----
    float* Vtr = sbuf;    // [64][68] reuse
#pragma unroll
    for (int mt = 0; mt < 2; mt++) {
#pragma unroll
        for (int nt = 0; nt < 6; nt++) {
            int col = wn * 48 + nt * 8 + 2 * ctg;
            int mat = col >> 6, c0 = col & 63;
            int r0 = row0 + wm * 32 + mt * 16 + g;
            if (mat == 0) {   // Q: pre-scale by SCL2, perm8 on h
                g_q[(size_t)r0 * HDIM + perm8(c0)]           = tf32r(acc[mt][nt][0] * SCL2);
                g_q[(size_t)r0 * HDIM + perm8(c0 + 1)]       = tf32r(acc[mt][nt][1] * SCL2);
                g_q[(size_t)(r0 + 8) * HDIM + perm8(c0)]     = tf32r(acc[mt][nt][2] * SCL2);
                g_q[(size_t)(r0 + 8) * HDIM + perm8(c0 + 1)] = tf32r(acc[mt][nt][3] * SCL2);
            } else if (mat == 1) {   // K: perm8 on h
                g_k[(size_t)r0 * HDIM + perm8(c0)]           = tf32r(acc[mt][nt][0]);
                g_k[(size_t)r0 * HDIM + perm8(c0 + 1)]       = tf32r(acc[mt][nt][1]);
                g_k[(size_t)(r0 + 8) * HDIM + perm8(c0)]     = tf32r(acc[mt][nt][2]);
                g_k[(size_t)(r0 + 8) * HDIM + perm8(c0 + 1)] = tf32r(acc[mt][nt][3]);
            } else {   // V: phi16 interleave on t
                int tl  = wm * 32 + mt * 16 + g;
                int tlp = (tl & ~15) + 4 * (g >> 1) + (g & 1);   // phi16(tl)
                Vtr[c0 * 68 + tlp]             = tf32r(acc[mt][nt][0]);
                Vtr[(c0 + 1) * 68 + tlp]       = tf32r(acc[mt][nt][1]);
                Vtr[c0 * 68 + tlp + 2]         = tf32r(acc[mt][nt][2]);  // phi16(tl+8)
                Vtr[(c0 + 1) * 68 + tlp + 2]   = tf32r(acc[mt][nt][3]);
            }
        }
    }
    __syncthreads();

    {
        const int b  = row0 >> 11;
        const int t0 = row0 & 2047;
#pragma unroll
        for (int i = 0; i < 4; i++) {
            int idx = t + 256 * i;
            int h = idx >> 4, c = (idx & 15) * 4;
            float4 v = *reinterpret_cast<const float4*>(&Vtr[h * 68 + c]);
            *reinterpret_cast<float4*>(
                &g_vt[((size_t)b * HDIM + h) * SEQ + t0 + c]) = v;
        }
    }
}

// ---------------------------------------------------------------------------
// Kernel 2: causal flash attention, split-K pieces.
// Q fragments held in REGISTERS (loaded once via LDG; no Q smem at all).
// smem: 2x K[64][72] + 2x V[64][80] = 77,824 B -> 2 CTAs/SM.
// ---------------------------------------------------------------------------
#define QP 72
#define VP 80
#define OFF_KB(buf) ((buf) * 64 * QP)
#define OFF_VB(buf) (2 * 64 * QP + (buf) * 64 * VP)
#define ATTN_SMEM_FLOATS (2 * 64 * QP + 2 * 64 * VP)
#define ATTN_SMEM_BYTES (ATTN_SMEM_FLOATS * 4)

__global__ __launch_bounds__(256, 2) void attn_kernel(float* __restrict__ out)
{
    extern __shared__ float smf[];
    const uint32_t smb = smem_u32(smf);

    const int t    = threadIdx.x;
    const int wid  = t >> 5;
    const int lane = t & 31;
    const int g    = lane >> 2;
    const int ctg  = lane & 3;
    const int qw   = wid * 16;
    const int b    = blockIdx.x;
    const int pc   = blockIdx.y;
    const int qt   = PQT[pc];
    const int p1   = PP1[pc];
    const bool split = (qt >= 8);
    const int ks   = p1 ? 16 : 0;
    const int ke   = (split && !p1) ? 16 : (2 * qt + 2);
    const int q0   = qt * 128;

    const float* kg0 = g_k  + ((size_t)b * SEQ) * HDIM;
    const float* vg0 = g_vt + ((size_t)b * HDIM) * SEQ;

    // stage K/V block ks into buf 0
    {
        const float* kg = kg0 + (size_t)ks * 64 * HDIM;
        const float* vg = vg0 + (size_t)ks * 64;
#pragma unroll
        for (int i = 0; i < 4; i++) {
            int idx = t + 256 * i;
            int r = idx >> 4, c = (idx & 15) * 4;
            cp16(smb + (uint32_t)(OFF_KB(0) + r * QP + c) * 4,
                 kg + (size_t)r * HDIM + c);
            cp16(smb + (uint32_t)(OFF_VB(0) + r * VP + c) * 4,
                 vg + (size_t)r * SEQ + c);
        }
    }
    CP_COMMIT();

    // load Q fragments into registers (once; g_q is L2-hot, pre-scaled)
    uint32_t qa[8][4];
    {
        const float* qg = g_q + ((size_t)b * SEQ + q0 + qw) * HDIM;
#pragma unroll
        for (int kss = 0; kss < 8; kss++) {
            const int kb = kss * 8 + 2 * ctg;
            float2 f0 = *reinterpret_cast<const float2*>(&qg[(size_t)g * HDIM + kb]);
            float2 f1 = *reinterpret_cast<const float2*>(&qg[(size_t)(g + 8) * HDIM + kb]);
            qa[kss][0] = __float_as_uint(f0.x); qa[kss][1] = __float_as_uint(f1.x);
            qa[kss][2] = __float_as_uint(f0.y); qa[kss][3] = __float_as_uint(f1.y);
        }
    }
    CP_WAIT0(); __syncthreads();

    float mrow[2] = { -CUDART_INF_F, -CUDART_INF_F };   // log2 domain
    float lrow[2] = { 0.f, 0.f };
    float o[8][4];
#pragma unroll
    for (int nt = 0; nt < 8; nt++)
#pragma unroll
        for (int i = 0; i < 4; i++) o[nt][i] = 0.f;

    for (int kt = ks; kt < ke; kt++) {
        const int cur = (kt - ks) & 1;

        if (kt + 1 < ke) {
            const float* kg = kg0 + (size_t)(kt + 1) * 64 * HDIM;
            const float* vg = vg0 + (size_t)(kt + 1) * 64;
#pragma unroll
            for (int i = 0; i < 4; i++) {
                int idx = t + 256 * i;
                int r = idx >> 4, c = (idx & 15) * 4;
                cp16(smb + (uint32_t)(OFF_KB(cur ^ 1) + r * QP + c) * 4,
                     kg + (size_t)r * HDIM + c);
                cp16(smb + (uint32_t)(OFF_VB(cur ^ 1) + r * VP + c) * 4,
                     vg + (size_t)r * SEQ + c);
            }
        }
        CP_COMMIT();

        const float* Kb = smf + OFF_KB(cur);
        const float* Vb = smf + OFF_VB(cur);

        // ---- S = Q K^T (Q pre-scaled, fragments in registers) ----
        float s[8][4];
#pragma unroll
        for (int nt = 0; nt < 8; nt++)
#pragma unroll
            for (int i = 0; i < 4; i++) s[nt][i] = 0.f;

#pragma unroll
        for (int kss = 0; kss < 8; kss++) {
            const int kb = kss * 8 + 2 * ctg;
#pragma unroll
            for (int nt = 0; nt < 8; nt++) {
                float2 kf = *reinterpret_cast<const float2*>(&Kb[(nt * 8 + g) * QP + kb]);
                uint32_t bb[2];
                bb[0] = __float_as_uint(kf.x); bb[1] = __float_as_uint(kf.y);
                mma_tf32(s[nt], qa[kss], bb);
            }
        }

        // ---- causal mask + online softmax (log2 domain; S pre-scaled) ----
        const bool tail = (kt >= 2 * qt);
        const int r0gl = q0 + qw + g, r1gl = r0gl + 8;
        const int kbase = kt * 64;
        float rm0 = -CUDART_INF_F, rm1 = -CUDART_INF_F;
#pragma unroll
        for (int nt = 0; nt < 8; nt++) {
            int cl = kbase + nt * 8 + 2 * ctg;
#pragma unroll
            for (int c = 0; c < 2; c++) {
                float v0 = s[nt][c];
                float v1 = s[nt][2 + c];
                if (tail) {
                    if (cl + c > r0gl) v0 = -1e30f;
                    if (cl + c > r1gl) v1 = -1e30f;
                }
                s[nt][c] = v0; s[nt][2 + c] = v1;
                rm0 = fmaxf(rm0, v0); rm1 = fmaxf(rm1, v1);
            }
        }
        rm0 = fmaxf(rm0, __shfl_xor_sync(0xffffffffu, rm0, 1));
        rm0 = fmaxf(rm0, __shfl_xor_sync(0xffffffffu, rm0, 2));
        rm1 = fmaxf(rm1, __shfl_xor_sync(0xffffffffu, rm1, 1));
        rm1 = fmaxf(rm1, __shfl_xor_sync(0xffffffffu, rm1, 2));

        float mn0 = fmaxf(mrow[0], rm0), mn1 = fmaxf(mrow[1], rm1);
        float fc0 = ex2(mrow[0] - mn0), fc1 = ex2(mrow[1] - mn1);
        float rs0 = 0.f, rs1 = 0.f;
#pragma unroll
        for (int nt = 0; nt < 8; nt++) {
#pragma unroll
            for (int c = 0; c < 2; c++) {
                float p0 = ex2(s[nt][c] - mn0);
                float p1 = ex2(s[nt][2 + c] - mn1);
                s[nt][c] = p0; s[nt][2 + c] = p1;
                rs0 += p0; rs1 += p1;
            }
        }
        rs0 += __shfl_xor_sync(0xffffffffu, rs0, 1);
        rs0 += __shfl_xor_sync(0xffffffffu, rs0, 2);
        rs1 += __shfl_xor_sync(0xffffffffu, rs1, 1);
        rs1 += __shfl_xor_sync(0xffffffffu, rs1, 2);

        lrow[0] = lrow[0] * fc0 + rs0;
        lrow[1] = lrow[1] * fc1 + rs1;
        mrow[0] = mn0; mrow[1] = mn1;
#pragma unroll
        for (int nt = 0; nt < 8; nt++) {
            o[nt][0] *= fc0; o[nt][1] *= fc0;
            o[nt][2] *= fc1; o[nt][3] *= fc1;
        }

        // ---- O += P V : LDS.128 V fragments serve ks-pairs (phi16 layout) ----
#pragma unroll
        for (int u = 0; u < 4; u++) {
            uint32_t a0[4], a1[4];
            a0[0] = __float_as_uint(s[2*u][0]);
            a0[1] = __float_as_uint(s[2*u][2]);
            a0[2] = __float_as_uint(s[2*u][1]);
            a0[3] = __float_as_uint(s[2*u][3]);
            a1[0] = __float_as_uint(s[2*u+1][0]);
            a1[1] = __float_as_uint(s[2*u+1][2]);
            a1[2] = __float_as_uint(s[2*u+1][1]);
            a1[3] = __float_as_uint(s[2*u+1][3]);
            const int kb = 16 * u + 4 * ctg;
#pragma unroll
            for (int nt = 0; nt < 8; nt++) {
                float4 vf = *reinterpret_cast<const float4*>(&Vb[(nt * 8 + g) * VP + kb]);
                uint32_t b0[2], b1[2];
                b0[0] = __float_as_uint(vf.x); b0[1] = __float_as_uint(vf.y);
                b1[0] = __float_as_uint(vf.z); b1[1] = __float_as_uint(vf.w);
                mma_tf32(o[nt], a0, b0);
                mma_tf32(o[nt], a1, b1);
            }
        }

        CP_WAIT0();
        __syncthreads();
    }

    // ---- epilogue ----
    const int limit = SEQ - g_nlim[b];
    const float qnan = __int_as_float(0x7FC00000);
    if (!split) {
        const int q0g = q0 + qw + g;
        const float inv0 = 1.f / lrow[0];
        const float inv1 = 1.f / lrow[1];
#pragma unroll
        for (int nt = 0; nt < 8; nt++) {
            int col = nt * 8 + 2 * ctg;
            float2 r0v, r1v;
            if (q0g >= limit) r0v = make_float2(qnan, qnan);
            else r0v = make_float2(o[nt][0] * inv0, o[nt][1] * inv0);
            if (q0g + 8 >= limit) r1v = make_float2(qnan, qnan);
            else r1v = make_float2(o[nt][2] * inv1, o[nt][3] * inv1);
            *reinterpret_cast<float2*>(&out[((size_t)b * SEQ + q0g) * HDIM + col]) = r0v;
            *reinterpret_cast<float2*>(&out[((size_t)b * SEQ + q0g + 8) * HDIM + col]) = r1v;
        }
    } else {
        const int slot = (b * 8 + (qt - 8)) * 2 + p1;
        float* po  = g_po  + (size_t)slot * 128 * 64;
        float* pml = g_pml + (size_t)slot * 256;
        const int r0l = qw + g, r1l = r0l + 8;
#pragma unroll
        for (int nt = 0; nt < 8; nt++) {
            int col = nt * 8 + 2 * ctg;
            *reinterpret_cast<float2*>(&po[r0l * 64 + col]) =
                make_float2(o[nt][0], o[nt][1]);
            *reinterpret_cast<float2*>(&po[r1l * 64 + col]) =
                make_float2(o[nt][2], o[nt][3]);
        }
        if (ctg == 0) {
            pml[r0l] = mrow[0]; pml[128 + r0l] = lrow[0];
            pml[r1l] = mrow[1]; pml[128 + r1l] = lrow[1];
        }
    }
}

// ---------------------------------------------------------------------------
// Kernel 3: combine split-K partials for qt 8..15 — massively parallel.
// (unchanged — validated R14/R15)
// ---------------------------------------------------------------------------
__global__ __launch_bounds__(256) void combine_kernel(float* __restrict__ out)
{
    const int qti = blockIdx.x >> 3;          // 0..7 -> qt = qti+8
    const int rg  = blockIdx.x & 7;           // row group of 16
    const int b   = blockIdx.y;
    const int slot0 = (b * 8 + qti) * 2;
    const float* O0  = g_po  + (size_t)slot0 * 8192;
    const float* O1  = O0 + 8192;
    const float* ml0 = g_pml + (size_t)slot0 * 256;
    const float* ml1 = ml0 + 256;

    const int t  = threadIdx.x;
    const int r  = rg * 16 + (t >> 4);
    const int c4 = (t & 15) * 4;

    const float m0 = ml0[r], l0 = ml0[128 + r];
    const float m1 = ml1[r], l1 = ml1[128 + r];
    const float mm = fmaxf(m0, m1);
    const float f0 = ex2(m0 - mm), f1 = ex2(m1 - mm);
    const float inv = 1.f / (l0 * f0 + l1 * f1);

    const int q = (qti + 8) * 128 + r;
    const int limit = SEQ - g_nlim[b];
    float* op = out + ((size_t)b * SEQ + q) * HDIM + c4;

    if (q >= limit) {
        const float qnan = __int_as_float(0x7FC00000);
        *reinterpret_cast<float4*>(op) = make_float4(qnan, qnan, qnan, qnan);
    } else {
        float4 a = *reinterpret_cast<const float4*>(&O0[r * 64 + c4]);
        float4 c = *reinterpret_cast<const float4*>(&O1[r * 64 + c4]);
        float4 rv;
        rv.x = (a.x * f0 + c.x * f1) * inv;
        rv.y = (a.y * f0 + c.y * f1) * inv;
        rv.z = (a.z * f0 + c.z * f1) * inv;
        rv.w = (a.w * f0 + c.w * f1) * inv;
        *reinterpret_cast<float4*>(op) = rv;
    }
}

// ---------------------------------------------------------------------------
extern "C" void kernel_launch(void* const* d_in, const int* in_sizes, int n_in,
                              void* d_out, int out_size)
{
    const float* x  = (const float*)d_in[0];
    const float* Wk = (const float*)d_in[1];
    const float* Wq = (const float*)d_in[2];
    const float* Wv = (const float*)d_in[3];
    const int*  idx = (const int*)d_in[4];
    float* out = (float*)d_out;

    (void)in_sizes; (void)n_in; (void)out_size;

    cudaFuncSetAttribute(proj_kernel,
                         cudaFuncAttributeMaxDynamicSharedMemorySize,
                         PJ_SMEM_BYTES);
    cudaFuncSetAttribute(attn_kernel,
                         cudaFuncAttributeMaxDynamicSharedMemorySize,
                         ATTN_SMEM_BYTES);

    prep_kernel<<<176, 256>>>(Wk, Wq, Wv, idx);
    proj_kernel<<<ROWS_TOTAL / 64, 256, PJ_SMEM_BYTES>>>(x);
    attn_kernel<<<dim3(BATCH, 24), 256, ATTN_SMEM_BYTES>>>(out);
    combine_kernel<<<dim3(64, BATCH), 256>>>(out);
}

// round 17
// speedup vs baseline: 1.8517x; 1.4941x over previous
#include <cuda_runtime.h>
#include <cuda_fp16.h>
#include <math_constants.h>
#include <cstdint>

// Problem shape (fixed): B=16, T=2048, C=512, H=64
#define BATCH 16
#define SEQ   2048
#define CDIM  512
#define HDIM  64
#define END_TOKEN 32000

#define ROWS_TOTAL (BATCH * SEQ)          // 32768
#define SCL2  0.06377946286456401f        // 512^-0.5 * log2(e)

__device__ __forceinline__ float ex2(float x) {
    float y; asm("ex2.approx.f32 %0,%1;" : "=f"(y) : "f"(x)); return y;
}
__device__ __forceinline__ uint32_t smem_u32(const void* p) {
    uint32_t a;
    asm("{ .reg .u64 t; cvta.to.shared.u64 t, %1; cvt.u32.u64 %0, t; }"
        : "=r"(a) : "l"(p));
    return a;
}
__device__ __forceinline__ void cp16(uint32_t dst, const void* src) {
    asm volatile("cp.async.cg.shared.global [%0], [%1], 16;"
                 :: "r"(dst), "l"(src) : "memory");
}
#define CP_COMMIT() asm volatile("cp.async.commit_group;" ::: "memory")
#define CP_WAIT0()  asm volatile("cp.async.wait_group 0;" ::: "memory")

// pack two fp32 -> one fp16x2 register (lo = first arg)
__device__ __forceinline__ uint32_t pack_h2(float lo, float hi) {
    uint32_t r;
    asm("cvt.rn.f16x2.f32 %0, %1, %2;" : "=r"(r) : "f"(hi), "f"(lo));
    return r;
}

// sigma16: logical i -> physical within 16-blocks. Slot c (4 fp16 = 8B) holds
// logical (2c, 2c+1, 2c+8, 2c+9) -> every m16n8k16 fragment is one LDS.64.
__device__ __forceinline__ int perm16(int i) {
    return (i & ~15) | ((((i & 7) >> 1)) << 2) | (((i >> 3) & 1) << 1) | (i & 1);
}

// m16n8k16 fp16 mma, fp32 accum (sm_80 portable -> fallback HMMA on sm_103)
__device__ __forceinline__ void mma_f16(float* d, const uint32_t* a, const uint32_t* b) {
    asm volatile(
        "mma.sync.aligned.m16n8k16.row.col.f32.f16.f16.f32 "
        "{%0,%1,%2,%3}, {%4,%5,%6,%7}, {%8,%9}, {%0,%1,%2,%3};"
        : "+f"(d[0]), "+f"(d[1]), "+f"(d[2]), "+f"(d[3])
        : "r"(a[0]), "r"(a[1]), "r"(a[2]), "r"(a[3]), "r"(b[0]), "r"(b[1]));
}

// Scratch (allocation-free rule: __device__ globals)
// g_q: fp16 [row][perm16(h)], pre-scaled by SCL2.  g_k: fp16 [row][perm16(h)].
// g_vt: fp16 [b][h][perm16-in-16 of t].  g_wt: fp16 W^T [mat][n][perm16(k)].
__device__ __half g_q[ROWS_TOTAL * HDIM];
__device__ __half g_k[ROWS_TOTAL * HDIM];
__device__ __half g_vt[BATCH * HDIM * SEQ];
__device__ __half g_wt[3 * HDIM * CDIM];
__device__ int    g_nlim[BATCH];          // SEQ - first_end (atomicMax; 0 = none)
// split-K partial results (fp32): 16 b x 8 heavy qt x 2 pieces
__device__ float g_po[BATCH * 8 * 2 * 128 * 64];
__device__ float g_pml[BATCH * 8 * 2 * 256];

// Piece table (heavy-first). qt<8: single direct piece. qt>=8: two pieces.
__device__ const int PQT[24] = {7,8,9,10,11,12,13,14,15,15, 6,14, 5,13,
                                4,12, 3,11, 2,10, 1,9, 0,8};
__device__ const int PP1[24] = {0,0,0,0,0,0,0,0,0,1, 0,1, 0,1,
                                0,1, 0,1, 0,1, 0,1, 0,1};

// ---------------------------------------------------------------------------
// Kernel 0: blocks 0..47 transpose W -> fp16 perm16 layout; blocks 48..175
// scan idx (atomicMax on g_nlim, idempotent across graph replays).
// ---------------------------------------------------------------------------
__global__ void prep_kernel(const float* __restrict__ Wk,
                            const float* __restrict__ Wq,
                            const float* __restrict__ Wv,
                            const int* __restrict__ idx)
{
    if (blockIdx.x < 48) {
        const int m  = blockIdx.x / 16;
        const int ks = blockIdx.x % 16;
        const float* src = (m == 0) ? Wq : (m == 1) ? Wk : Wv;
        __half* dst = g_wt + (size_t)m * HDIM * CDIM;
        for (int i = threadIdx.x; i < 32 * 64; i += 256) {
            int k = ks * 32 + (i & 31);
            int n = i >> 5;
            dst[(size_t)n * CDIM + perm16(k)] =
                __float2half_rn(src[(size_t)k * HDIM + n]);
        }
    } else {
        const int blk = blockIdx.x - 48;
        const int b   = blk >> 3;
        const int seg = blk & 7;
        const int t0  = seg * 256 + threadIdx.x;
        if (idx[(size_t)b * SEQ + t0] == END_TOKEN)
            atomicMax(&g_nlim[b], SEQ - t0);
    }
}

// ---------------------------------------------------------------------------
// Kernel 1: QKV projection via fp16 m16n8k16 mma (64 rows x 192 cols per CTA).
// smem (halves): A bufs 2x64x32 @0, B bufs 2x192x32 @4096. Total 32 KB.
// Swizzle: phys slot = slot ^ ((row&2)<<1).  K=32 chunk -> 2 MMA k-steps.
// ---------------------------------------------------------------------------
#define PJ_A(buf) ((buf) * 2048)
#define PJ_B(buf) (4096 + (buf) * 6144)
#define PJ_SMEM_BYTES 32768

__global__ __launch_bounds__(256, 2) void proj_kernel(const float* __restrict__ x)
{
    extern __shared__ __half smh[];
    const uint32_t smb = smem_u32(smh);

    const int t    = threadIdx.x;
    const int wid  = t >> 5;
    const int lane = t & 31;
    const int g    = lane >> 2;
    const int ctg  = lane & 3;
    const int wm   = wid >> 2;     // 0..1
    const int wn   = wid & 3;      // 0..3
    const int row0 = blockIdx.x * 64;

    // A staging: thread r = t>>2 (0..63), q = t&3 covers logical k [8q,8q+8)
    const int ar = t >> 2, aq = t & 3;
    const int aG = aq >> 1, ahw = aq & 1;    // k16-group, halfword-within-slot
    // B staging: 768 16B-chunks, 3 per thread
    const int bn0 = t >> 2, bch = t & 3;

    float acc[2][6][4];
#pragma unroll
    for (int mt = 0; mt < 2; mt++)
#pragma unroll
        for (int nt = 0; nt < 6; nt++)
#pragma unroll
            for (int i = 0; i < 4; i++) acc[mt][nt][i] = 0.f;

    // prologue: cp.async B chunk0; prefetch x chunk0
    {
#pragma unroll
        for (int j = 0; j < 3; j++) {
            int n = bn0 + 64 * j;
            int chp = bch ^ ((n & 2) ? 2 : 0);
            cp16(smb + (uint32_t)(PJ_B(0) + n * 32 + chp * 8) * 2,
                 g_wt + (size_t)n * CDIM + bch * 8);
        }
        CP_COMMIT();
    }
    float4 pa0, pa1;
    {
        const float* xp = x + (size_t)(row0 + ar) * CDIM + aq * 8;
        pa0 = *reinterpret_cast<const float4*>(xp);
        pa1 = *reinterpret_cast<const float4*>(xp + 4);
    }

    for (int kc = 0; kc < 16; kc++) {
        const int buf = kc & 1;

        // store A chunk: 4 half2 STS.32 per thread, sigma16+swizzle
        {
            __half* A = smh + PJ_A(buf) + ar * 32;
            const int xr = (ar & 2) << 1;
            const float pf[8] = { pa0.x, pa0.y, pa0.z, pa0.w,
                                  pa1.x, pa1.y, pa1.z, pa1.w };
#pragma unroll
            for (int c = 0; c < 4; c++) {
                int slot = (aG * 4 + c) ^ xr;
                *reinterpret_cast<uint32_t*>(&A[slot * 4 + ahw * 2]) =
                    pack_h2(pf[2 * c], pf[2 * c + 1]);
            }
        }
        CP_WAIT0();
        __syncthreads();

        if (kc < 15) {
            const int ko = (kc + 1) * 32;
#pragma unroll
            for (int j = 0; j < 3; j++) {
                int n = bn0 + 64 * j;
                int chp = bch ^ ((n & 2) ? 2 : 0);
                cp16(smb + (uint32_t)(PJ_B(buf ^ 1) + n * 32 + chp * 8) * 2,
                     g_wt + (size_t)n * CDIM + ko + bch * 8);
            }
            CP_COMMIT();
            const float* xp = x + (size_t)(row0 + ar) * CDIM + ko + aq * 8;
            pa0 = *reinterpret_cast<const float4*>(xp);
            pa1 = *reinterpret_cast<const float4*>(xp + 4);
        }

        const __half* As = smh + PJ_A(buf);
        const __half* Bs = smh + PJ_B(buf);
        const int xr = (g & 2) << 1;
#pragma unroll
        for (int ks = 0; ks < 2; ks++) {
            const int phys = (ks * 4 + ctg) ^ xr;
            uint32_t a[2][4];
#pragma unroll
            for (int mt = 0; mt < 2; mt++) {
                int row = wm * 32 + mt * 16;
                uint2 v0 = *reinterpret_cast<const uint2*>(&As[(row + g) * 32 + phys * 4]);
                uint2 v1 = *reinterpret_cast<const uint2*>(&As[(row + g + 8) * 32 + phys * 4]);
                a[mt][0] = v0.x; a[mt][1] = v1.x; a[mt][2] = v0.y; a[mt][3] = v1.y;
            }
#pragma unroll
            for (int nt = 0; nt < 6; nt++) {
                int n = wn * 48 + nt * 8 + g;
                uint2 vb = *reinterpret_cast<const uint2*>(&Bs[n * 32 + phys * 4]);
                uint32_t b[2] = { vb.x, vb.y };
                mma_f16(acc[0][nt], a[0], b);
                mma_f16(acc[1][nt], a[1], b);
            }
        }
    }
    __syncthreads();   // all MMAs done before smem reuse as Vtr

    // ---- epilogue: Q (pre-scaled) / K fp16 perm16; V via smem transpose ----
    __half* Vtr = smh;    // [64 h][80] halves
#pragma unroll
    for (int mt = 0; mt < 2; mt++) {
#pragma unroll
        for (int nt = 0; nt < 6; nt++) {
            int col = wn * 48 + nt * 8 + 2 * ctg;
            int mat = col >> 6, c0 = col & 63;
            int r0 = row0 + wm * 32 + mt * 16 + g;
            if (mat == 0) {
                int p = perm16(c0);
                *reinterpret_cast<__half2*>(&g_q[(size_t)r0 * HDIM + p]) =
                    __floats2half2_rn(acc[mt][nt][0] * SCL2, acc[mt][nt][1] * SCL2);
                *reinterpret_cast<__half2*>(&g_q[(size_t)(r0 + 8) * HDIM + p]) =
                    __floats2half2_rn(acc[mt][nt][2] * SCL2, acc[mt][nt][3] * SCL2);
            } else if (mat == 1) {
                int p = perm16(c0);
                *reinterpret_cast<__half2*>(&g_k[(size_t)r0 * HDIM + p]) =
                    __floats2half2_rn(acc[mt][nt][0], acc[mt][nt][1]);
                *reinterpret_cast<__half2*>(&g_k[(size_t)(r0 + 8) * HDIM + p]) =
                    __floats2half2_rn(acc[mt][nt][2], acc[mt][nt][3]);
            } else {
                int tl = wm * 32 + mt * 16 + g;          // tl&8 == 0
                int p0 = perm16(tl);                     // perm16(tl+8) = p0+2
                Vtr[c0 * 80 + p0]           = __float2half_rn(acc[mt][nt][0]);
                Vtr[(c0 + 1) * 80 + p0]     = __float2half_rn(acc[mt][nt][1]);
                Vtr[c0 * 80 + p0 + 2]       = __float2half_rn(acc[mt][nt][2]);
                Vtr[(c0 + 1) * 80 + p0 + 2] = __float2half_rn(acc[mt][nt][3]);
            }
        }
    }
    __syncthreads();

    // coalesced V writes: 64 h-rows x 64 t fp16 (16B bursts)
    {
        const int b  = row0 >> 11;
        const int t0 = row0 & 2047;
#pragma unroll
        for (int i = 0; i < 2; i++) {
            int idx = t + 256 * i;
            int h = idx >> 3, c8 = (idx & 7) * 8;
            uint4 v = *reinterpret_cast<const uint4*>(&Vtr[h * 80 + c8]);
            *reinterpret_cast<uint4*>(
                &g_vt[((size_t)b * HDIM + h) * SEQ + t0 + c8]) = v;
        }
    }
}

// ---------------------------------------------------------------------------
// Kernel 2: causal flash attention, split-K pieces, fp16 MMAs.
// Q fragments in registers (LDG). K/V fp16 smem, rotation swizzle
// phys = (slot + 4*(row&3)) & 15. smem: 2x(K 8KB) + 2x(V 8KB) = 32 KB.
// ---------------------------------------------------------------------------
#define OFF_KB(buf) ((buf) * 4096)
#define OFF_VB(buf) (8192 + (buf) * 4096)
#define ATTN_SMEM_BYTES 32768

__global__ __launch_bounds__(256, 2) void attn_kernel(float* __restrict__ out)
{
    extern __shared__ __half smh[];
    const uint32_t smb = smem_u32(smh);

    const int t    = threadIdx.x;
    const int wid  = t >> 5;
    const int lane = t & 31;
    const int g    = lane >> 2;
    const int ctg  = lane & 3;
    const int qw   = wid * 16;
    const int b    = blockIdx.x;
    const int pc   = blockIdx.y;
    const int qt   = PQT[pc];
    const int p1   = PP1[pc];
    const bool split = (qt >= 8);
    const int ks   = p1 ? 16 : 0;
    const int ke   = (split && !p1) ? 16 : (2 * qt + 2);
    const int q0   = qt * 128;

    const __half* kg0 = g_k  + ((size_t)b * SEQ) * HDIM;
    const __half* vg0 = g_vt + ((size_t)b * HDIM) * SEQ;

    // staging coords: 512 16B-chunks per tile, 2 per thread
    const int sr0 = t >> 3, sch = t & 7;

    // stage K/V block ks into buf 0
    {
        const __half* kg = kg0 + (size_t)ks * 64 * HDIM;
        const __half* vg = vg0 + (size_t)ks * 64;
#pragma unroll
        for (int i = 0; i < 2; i++) {
            int r = sr0 + 32 * i;
            int chp = (sch + 2 * (r & 3)) & 7;
            cp16(smb + (uint32_t)(OFF_KB(0) + r * 64 + chp * 8) * 2,
                 kg + (size_t)r * HDIM + sch * 8);
            cp16(smb + (uint32_t)(OFF_VB(0) + r * 64 + chp * 8) * 2,
                 vg + (size_t)r * SEQ + sch * 8);
        }
    }
    CP_COMMIT();

    // load Q fragments into registers (once; pre-scaled, perm16 layout)
    uint32_t qa[4][4];
    {
        const __half* qg = g_q + ((size_t)(b * SEQ + q0 + qw)) * HDIM;
#pragma unroll
        for (int kss = 0; kss < 4; kss++) {
            int slot = kss * 4 + ctg;
            uint2 v0 = *reinterpret_cast<const uint2*>(&qg[(size_t)g * HDIM + slot * 4]);
            uint2 v1 = *reinterpret_cast<const uint2*>(&qg[(size_t)(g + 8) * HDIM + slot * 4]);
            qa[kss][0] = v0.x; qa[kss][1] = v1.x; qa[kss][2] = v0.y; qa[kss][3] = v1.y;
        }
    }
    CP_WAIT0(); __syncthreads();

    float mrow[2] = { -CUDART_INF_F, -CUDART_INF_F };   // log2 domain
    float lrow[2] = { 0.f, 0.f };
    float o[8][4];
#pragma unroll
    for (int nt = 0; nt < 8; nt++)
#pragma unroll
        for (int i = 0; i < 4; i++) o[nt][i] = 0.f;

    const int rot = 4 * (g & 3);   // V/K fragment rotation (row&3 == g&3)

    for (int kt = ks; kt < ke; kt++) {
        const int cur = (kt - ks) & 1;

        if (kt + 1 < ke) {
            const __half* kg = kg0 + (size_t)(kt + 1) * 64 * HDIM;
            const __half* vg = vg0 + (size_t)(kt + 1) * 64;
#pragma unroll
            for (int i = 0; i < 2; i++) {
                int r = sr0 + 32 * i;
                int chp = (sch + 2 * (r & 3)) & 7;
                cp16(smb + (uint32_t)(OFF_KB(cur ^ 1) + r * 64 + chp * 8) * 2,
                     kg + (size_t)r * HDIM + sch * 8);
                cp16(smb + (uint32_t)(OFF_VB(cur ^ 1) + r * 64 + chp * 8) * 2,
                     vg + (size_t)r * SEQ + sch * 8);
            }
        }
        CP_COMMIT();

        const __half* Kb = smh + OFF_KB(cur);
        const __half* Vb = smh + OFF_VB(cur);

        // ---- S = Q K^T : 4 k-steps x 8 n-tiles ----
        float s[8][4];
#pragma unroll
        for (int nt = 0; nt < 8; nt++)
#pragma unroll
            for (int i = 0; i < 4; i++) s[nt][i] = 0.f;

#pragma unroll
        for (int kss = 0; kss < 4; kss++) {
            const int slot = kss * 4 + ctg;
#pragma unroll
            for (int nt = 0; nt < 8; nt++) {
                int row = nt * 8 + g;
                int phys = (slot + rot) & 15;
                uint2 kf = *reinterpret_cast<const uint2*>(&Kb[row * 64 + phys * 4]);
                uint32_t bb[2] = { kf.x, kf.y };
                mma_f16(s[nt], qa[kss], bb);
            }
        }

        // ---- causal mask + online softmax (log2 domain; S pre-scaled) ----
        const bool tail = (kt >= 2 * qt);
        const int r0gl = q0 + qw + g, r1gl = r0gl + 8;
        const int kbase = kt * 64;
        float rm0 = -CUDART_INF_F, rm1 = -CUDART_INF_F;
#pragma unroll
        for (int nt = 0; nt < 8; nt++) {
            int cl = kbase + nt * 8 + 2 * ctg;
#pragma unroll
            for (int c = 0; c < 2; c++) {
                float v0 = s[nt][c];
                float v1 = s[nt][2 + c];
                if (tail) {
                    if (cl + c > r0gl) v0 = -1e30f;
                    if (cl + c > r1gl) v1 = -1e30f;
                }
                s[nt][c] = v0; s[nt][2 + c] = v1;
                rm0 = fmaxf(rm0, v0); rm1 = fmaxf(rm1, v1);
            }
        }
        rm0 = fmaxf(rm0, __shfl_xor_sync(0xffffffffu, rm0, 1));
        rm0 = fmaxf(rm0, __shfl_xor_sync(0xffffffffu, rm0, 2));
        rm1 = fmaxf(rm1, __shfl_xor_sync(0xffffffffu, rm1, 1));
        rm1 = fmaxf(rm1, __shfl_xor_sync(0xffffffffu, rm1, 2));

        float mn0 = fmaxf(mrow[0], rm0), mn1 = fmaxf(mrow[1], rm1);
        float fc0 = ex2(mrow[0] - mn0), fc1 = ex2(mrow[1] - mn1);
        float rs0 = 0.f, rs1 = 0.f;
#pragma unroll
        for (int nt = 0; nt < 8; nt++) {
#pragma unroll
            for (int c = 0; c < 2; c++) {
                float p0 = ex2(s[nt][c] - mn0);
                float p1 = ex2(s[nt][2 + c] - mn1);
                s[nt][c] = p0; s[nt][2 + c] = p1;
                rs0 += p0; rs1 += p1;
            }
        }
        rs0 += __shfl_xor_sync(0xffffffffu, rs0, 1);
        rs0 += __shfl_xor_sync(0xffffffffu, rs0, 2);
        rs1 += __shfl_xor_sync(0xffffffffu, rs1, 1);
        rs1 += __shfl_xor_sync(0xffffffffu, rs1, 2);

        lrow[0] = lrow[0] * fc0 + rs0;
        lrow[1] = lrow[1] * fc1 + rs1;
        mrow[0] = mn0; mrow[1] = mn1;
#pragma unroll
        for (int nt = 0; nt < 8; nt++) {
            o[nt][0] *= fc0; o[nt][1] *= fc0;
            o[nt][2] *= fc1; o[nt][3] *= fc1;
        }

        // ---- O += P V : P packed to fp16 in registers ----
#pragma unroll
        for (int u = 0; u < 4; u++) {
            uint32_t a[4];
            a[0] = pack_h2(s[2*u][0],   s[2*u][1]);
            a[1] = pack_h2(s[2*u][2],   s[2*u][3]);
            a[2] = pack_h2(s[2*u+1][0], s[2*u+1][1]);
            a[3] = pack_h2(s[2*u+1][2], s[2*u+1][3]);
            const int slot = u * 4 + ctg;
#pragma unroll
            for (int nt = 0; nt < 8; nt++) {
                int row = nt * 8 + g;
                int phys = (slot + rot) & 15;
                uint2 vf = *reinterpret_cast<const uint2*>(&Vb[row * 64 + phys * 4]);
                uint32_t bb[2] = { vf.x, vf.y };
                mma_f16(o[nt], a, bb);
            }
        }

        CP_WAIT0();
        __syncthreads();
    }

    // ---- epilogue ----
    const int limit = SEQ - g_nlim[b];
    const float qnan = __int_as_float(0x7FC00000);
    if (!split) {
        const int q0g = q0 + qw + g;
        const float inv0 = 1.f / lrow[0];
        const float inv1 = 1.f / lrow[1];
#pragma unroll
        for (int nt = 0; nt < 8; nt++) {
            int col = nt * 8 + 2 * ctg;
            float2 r0v, r1v;
            if (q0g >= limit) r0v = make_float2(qnan, qnan);
            else r0v = make_float2(o[nt][0] * inv0, o[nt][1] * inv0);
            if (q0g + 8 >= limit) r1v = make_float2(qnan, qnan);
            else r1v = make_float2(o[nt][2] * inv1, o[nt][3] * inv1);
            *reinterpret_cast<float2*>(&out[((size_t)b * SEQ + q0g) * HDIM + col]) = r0v;
            *reinterpret_cast<float2*>(&out[((size_t)b * SEQ + q0g + 8) * HDIM + col]) = r1v;
        }
    } else {
        const int slot = (b * 8 + (qt - 8)) * 2 + p1;
        float* po  = g_po  + (size_t)slot * 8192;
        float* pml = g_pml + (size_t)slot * 256;
        const int r0l = qw + g, r1l = r0l + 8;
#pragma unroll
        for (int nt = 0; nt < 8; nt++) {
            int col = nt * 8 + 2 * ctg;
            *reinterpret_cast<float2*>(&po[r0l * 64 + col]) =
                make_float2(o[nt][0], o[nt][1]);
            *reinterpret_cast<float2*>(&po[r1l * 64 + col]) =
                make_float2(o[nt][2], o[nt][3]);
        }
        if (ctg == 0) {
            pml[r0l] = mrow[0]; pml[128 + r0l] = lrow[0];
            pml[r1l] = mrow[1]; pml[128 + r1l] = lrow[1];
        }
    }
}

// ---------------------------------------------------------------------------
// Kernel 3: combine split-K partials for qt 8..15 — massively parallel.
// (unchanged — validated R14/R15/R16)
// ---------------------------------------------------------------------------
__global__ __launch_bounds__(256) void combine_kernel(float* __restrict__ out)
{
    const int qti = blockIdx.x >> 3;
    const int rg  = blockIdx.x & 7;
    const int b   = blockIdx.y;
    const int slot0 = (b * 8 + qti) * 2;
    const float* O0  = g_po  + (size_t)slot0 * 8192;
    const float* O1  = O0 + 8192;
    const float* ml0 = g_pml + (size_t)slot0 * 256;
    const float* ml1 = ml0 + 256;

    const int t  = threadIdx.x;
    const int r  = rg * 16 + (t >> 4);
    const int c4 = (t & 15) * 4;

    const float m0 = ml0[r], l0 = ml0[128 + r];
    const float m1 = ml1[r], l1 = ml1[128 + r];
    const float mm = fmaxf(m0, m1);
    const float f0 = ex2(m0 - mm), f1 = ex2(m1 - mm);
    const float inv = 1.f / (l0 * f0 + l1 * f1);

    const int q = (qti + 8) * 128 + r;
    const int limit = SEQ - g_nlim[b];
    float* op = out + ((size_t)b * SEQ + q) * HDIM + c4;

    if (q >= limit) {
        const float qnan = __int_as_float(0x7FC00000);
        *reinterpret_cast<float4*>(op) = make_float4(qnan, qnan, qnan, qnan);
    } else {
        float4 a = *reinterpret_cast<const float4*>(&O0[r * 64 + c4]);
        float4 c = *reinterpret_cast<const float4*>(&O1[r * 64 + c4]);
        float4 rv;
        rv.x = (a.x * f0 + c.x * f1) * inv;
        rv.y = (a.y * f0 + c.y * f1) * inv;
        rv.z = (a.z * f0 + c.z * f1) * inv;
        rv.w = (a.w * f0 + c.w * f1) * inv;
        *reinterpret_cast<float4*>(op) = rv;
    }
}

// ---------------------------------------------------------------------------
extern "C" void kernel_launch(void* const* d_in, const int* in_sizes, int n_in,
                              void* d_out, int out_size)
{
    const float* x  = (const float*)d_in[0];
    const float* Wk = (const float*)d_in[1];
    const float* Wq = (const float*)d_in[2];
    const float* Wv = (const float*)d_in[3];
    const int*  idx = (const int*)d_in[4];
    float* out = (float*)d_out;

    (void)in_sizes; (void)n_in; (void)out_size;

    cudaFuncSetAttribute(proj_kernel,
                         cudaFuncAttributeMaxDynamicSharedMemorySize,
                         PJ_SMEM_BYTES);
    cudaFuncSetAttribute(attn_kernel,
                         cudaFuncAttributeMaxDynamicSharedMemorySize,
                         ATTN_SMEM_BYTES);

    prep_kernel<<<176, 256>>>(Wk, Wq, Wv, idx);
    proj_kernel<<<ROWS_TOTAL / 64, 256, PJ_SMEM_BYTES>>>(x);
    attn_kernel<<<dim3(BATCH, 24), 256, ATTN_SMEM_BYTES>>>(out);
    combine_kernel<<<dim3(64, BATCH), 256>>>(out);
}